// round 8
// baseline (speedup 1.0000x reference)
#include <cuda_runtime.h>
#include <cuda_bf16.h>
#include <cstdint>

// Shapes (fixed by the problem)
#define B_   2
#define S_   2048
#define H_   1024
#define NH_  16
#define M_   512
#define D_   64
#define CAT_ (H_ + M_)   // 1536

// ---------------- scratch (static device memory; no allocations allowed) ---
__device__ float g_q  [(long long)B_*S_*H_];
__device__ float g_k  [(long long)B_*S_*H_];
__device__ float g_v  [(long long)B_*S_*H_];
__device__ float g_mq [(long long)B_*S_*M_];
__device__ float g_mk [(long long)B_*S_*M_];
__device__ float g_med[(long long)B_*S_*S_];
__device__ float g_cat[(long long)B_*S_*CAT_];
__device__ float g_x  [(long long)B_*S_*H_];
__device__ float g_part[(long long)B_*NH_*S_*32];   // per-tile row partial sums
__device__ float g_minv[(long long)B_*S_];          // med row inv sums
__device__ float g_pinv[(long long)B_*NH_*S_];      // probs row inv sums

// ---------------- helpers ----------------
__device__ __forceinline__ uint32_t smem_to_u32(const void* p) {
    uint32_t a;
    asm("{ .reg .u64 t; cvta.to.shared.u64 t, %1; cvt.u32.u64 %0, t; }" : "=r"(a) : "l"(p));
    return a;
}
__device__ __forceinline__ void ldmx4(uint32_t* r, uint32_t addr) {
    asm volatile("ldmatrix.sync.aligned.m8n8.x4.shared.b16 {%0,%1,%2,%3}, [%4];"
        : "=r"(r[0]), "=r"(r[1]), "=r"(r[2]), "=r"(r[3]) : "r"(addr));
}
__device__ __forceinline__ void ldmx4t(uint32_t* r, uint32_t addr) {
    asm volatile("ldmatrix.sync.aligned.m8n8.x4.trans.shared.b16 {%0,%1,%2,%3}, [%4];"
        : "=r"(r[0]), "=r"(r[1]), "=r"(r[2]), "=r"(r[3]) : "r"(addr));
}
__device__ __forceinline__ void mma16816(float* d, const uint32_t* a, const uint32_t* b) {
    asm volatile(
        "mma.sync.aligned.m16n8k16.row.col.f32.bf16.bf16.f32 "
        "{%0,%1,%2,%3}, {%4,%5,%6,%7}, {%8,%9}, {%0,%1,%2,%3};"
        : "+f"(d[0]), "+f"(d[1]), "+f"(d[2]), "+f"(d[3])
        : "r"(a[0]), "r"(a[1]), "r"(a[2]), "r"(a[3]), "r"(b[0]), "r"(b[1]));
}

struct alignas(16) BF8 { __nv_bfloat16 v[8]; };
__device__ __forceinline__ void split8(const float* f, BF8& hi, BF8& lo) {
    #pragma unroll
    for (int i = 0; i < 8; ++i) {
        __nv_bfloat16 h = __float2bfloat16(f[i]);
        hi.v[i] = h;
        lo.v[i] = __float2bfloat16(f[i] - __bfloat162float(h));
    }
}

// epilogue/flag bits
#define F_TRANS   1
#define F_EXP     2
#define F_ADDNORM 4
#define F_NORMA   8

#define A_STRIDE_B 80
#define BNT_STRIDE_B 80

// ---------------- universal pipelined bf16-split mma.sync GEMM ----------------
// BM=128 fixed; BN template (64: 256 thr / 8 warps, 128: 512 thr / 16 warps).
// C[M,N] = alpha * A[M,K] @ op(B) (+bias[col]) (+addScale*Add[row,col]*AddInv[row])
// F_EXP: C = exp(val); per-row tile partial sums -> Psum[(zP+row)*32 + bx]
// F_NORMA: A rows scaled by AInv[zNi+row] during load AND written back to gmem.
template<int BN, int BLK>
__global__ void __launch_bounds__(BLK, (BN == 64) ? 2 : 1) k_mma_gemm(
    const float* __restrict__ A, const float* __restrict__ B,
    const float* __restrict__ bias, const float* __restrict__ Add,
    const float* __restrict__ AddInv, const float* __restrict__ AInv,
    float* __restrict__ C, float* __restrict__ Psum,
    int K, int lda, int ldb, int ldc, int ldadd, int zdiv,
    long long sA1, long long sA0, long long sB1, long long sB0,
    long long sC1, long long sC0, long long sAdd1, long long sAdd0,
    long long sAi1, long long sAi0, long long sNi1, long long sNi0,
    long long sP1, long long sP0,
    float alpha, float addScale, int flags)
{
    constexpr int NW      = BN / 32;              // n-warps
    constexpr int BNN_ST  = (BN == 64) ? 144 : 272;
    constexpr int BSZ     = (BN == 64) ? 5120 : 10240;
    constexpr int OFF_BHI = 20480;
    constexpr int OFF_BLO = 20480 + BSZ;
    constexpr int STAGE   = 20480 + 2 * BSZ;
    constexpr int APT     = 4096 / BLK;           // A floats per thread (16 / 8)
    constexpr int CPR     = 32 / APT;             // A chunks per row (2 / 4)
    constexpr int NCPR    = BN / 8;               // B-NN chunks per row

    extern __shared__ __align__(16) uint8_t smem[];
    const uint32_t sb = smem_to_u32(smem);

    const int tid = threadIdx.x;
    const int wid = tid >> 5;
    const int lane = tid & 31;

    const int z = blockIdx.z;
    const int z1 = z / zdiv, z0 = z % zdiv;
    A += z1 * sA1 + z0 * sA0;
    B += z1 * sB1 + z0 * sB0;
    C += z1 * sC1 + z0 * sC0;
    if (Add) Add += z1 * sAdd1 + z0 * sAdd0;
    const long long ziAdd = z1 * sAi1 + z0 * sAi0;
    const long long ziN   = z1 * sNi1 + z0 * sNi0;
    const long long ziP   = z1 * sP1  + z0 * sP0;

    const int m0 = blockIdx.y * 128;
    const int n0 = blockIdx.x * BN;

    const int wm0 = (wid / NW) * 32;
    const int wn0 = (wid % NW) * 32;

    // ldmatrix per-lane offsets (within one stage buffer)
    const uint32_t aLane = (uint32_t)(wm0 + (lane & 15)) * A_STRIDE_B + ((lane >> 4) << 3) * 2;
    const uint32_t bLaneNT = (uint32_t)(wn0 + ((lane >> 1) & 8) + (lane & 7)) * BNT_STRIDE_B
                           + (uint32_t)(lane & 8) * 2;
    const uint32_t bLaneNN = (uint32_t)(lane & 15) * BNN_ST
                           + (uint32_t)(wn0 + ((lane >> 1) & 8)) * 2;

    // global-load coords
    const int ar = tid / CPR, ac = (tid % CPR) * APT;  // A
    const int ntr = tid >> 2, ntk = (tid & 3) * 8;     // B NT: BLK/4 rows (== BN)
    const int nnr = tid / NCPR, nnc = (tid % NCPR) * 8; // B NN: 32 rows

    const float aScale = (flags & F_NORMA) ? AInv[ziN + m0 + ar] : 1.0f;

    float acc[2][4][4];
    #pragma unroll
    for (int i = 0; i < 2; ++i)
        #pragma unroll
        for (int j = 0; j < 4; ++j)
            #pragma unroll
            for (int e = 0; e < 4; ++e) acc[i][j][e] = 0.0f;

    float fA[APT], fB[8];

#define LOAD_TILE(k0v) {                                                            \
        const float* srcA = A + (long long)(m0 + ar) * lda + (k0v) + ac;            \
        _Pragma("unroll") for (int e = 0; e < APT; e += 4)                          \
            *(float4*)(fA + e) = *(const float4*)(srcA + e);                        \
        if (flags & F_NORMA) {                                                      \
            _Pragma("unroll") for (int e = 0; e < APT; ++e) fA[e] *= aScale;        \
            float* wb = const_cast<float*>(srcA);                                   \
            _Pragma("unroll") for (int e = 0; e < APT; e += 4)                      \
                *(float4*)(wb + e) = *(float4*)(fA + e);                            \
        }                                                                           \
        if (flags & F_TRANS) {                                                      \
            const float* srcB = B + (long long)(n0 + ntr) * ldb + (k0v) + ntk;      \
            *(float4*)(fB)     = *(const float4*)(srcB);                            \
            *(float4*)(fB + 4) = *(const float4*)(srcB + 4);                        \
        } else {                                                                    \
            const float* srcB = B + (long long)((k0v) + nnr) * ldb + n0 + nnc;      \
            *(float4*)(fB)     = *(const float4*)(srcB);                            \
            *(float4*)(fB + 4) = *(const float4*)(srcB + 4);                        \
        }                                                                           \
    }

#define STORE_TILE(st) {                                                            \
        uint8_t* sp = smem + (st) * STAGE;                                          \
        _Pragma("unroll") for (int gg = 0; gg < APT / 8; ++gg) {                    \
            BF8 h, l; split8(fA + gg * 8, h, l);                                    \
            const uint32_t offA = (uint32_t)ar * A_STRIDE_B + (ac + gg * 8) * 2;    \
            *(uint4*)(sp + 0     + offA) = *(const uint4*)&h;                       \
            *(uint4*)(sp + 10240 + offA) = *(const uint4*)&l;                       \
        }                                                                           \
        BF8 hb, lb2; split8(fB, hb, lb2);                                           \
        const uint32_t offB = (flags & F_TRANS)                                     \
            ? (uint32_t)ntr * BNT_STRIDE_B + ntk * 2                                \
            : (uint32_t)nnr * BNN_ST + nnc * 2;                                     \
        *(uint4*)(sp + OFF_BHI + offB) = *(const uint4*)&hb;                        \
        *(uint4*)(sp + OFF_BLO + offB) = *(const uint4*)&lb2;                       \
    }

    const int nIter = K >> 5;   // BK = 32

    LOAD_TILE(0);
    STORE_TILE(0);
    __syncthreads();

    int cur = 0;
    for (int it = 0; it < nIter; ++it) {
        const bool hasNext = (it + 1 < nIter);
        if (hasNext) LOAD_TILE((it + 1) << 5);

        const uint32_t stb = sb + cur * STAGE;
        #pragma unroll
        for (int kk = 0; kk < 2; ++kk) {
            uint32_t ahi[2][4], alo[2][4], bhi[2][4], blo[2][4];
            const uint32_t akk = aLane + (uint32_t)(kk * 16) * 2;
            #pragma unroll
            for (int mi = 0; mi < 2; ++mi) {
                const uint32_t off = akk + (uint32_t)(mi * 16) * A_STRIDE_B;
                ldmx4(ahi[mi], stb + 0 + off);
                ldmx4(alo[mi], stb + 10240 + off);
            }
            if (flags & F_TRANS) {
                const uint32_t bkk = bLaneNT + (uint32_t)(kk * 16) * 2;
                #pragma unroll
                for (int nj = 0; nj < 2; ++nj) {
                    const uint32_t off = bkk + (uint32_t)(nj * 16) * BNT_STRIDE_B;
                    ldmx4(bhi[nj], stb + OFF_BHI + off);
                    ldmx4(blo[nj], stb + OFF_BLO + off);
                }
            } else {
                const uint32_t bkk = bLaneNN + (uint32_t)(kk * 16) * BNN_ST;
                #pragma unroll
                for (int nj = 0; nj < 2; ++nj) {
                    const uint32_t off = bkk + (uint32_t)(nj * 16) * 2;
                    ldmx4t(bhi[nj], stb + OFF_BHI + off);
                    ldmx4t(blo[nj], stb + OFF_BLO + off);
                }
            }
            #pragma unroll
            for (int mi = 0; mi < 2; ++mi)
                #pragma unroll
                for (int jj = 0; jj < 4; ++jj) {
                    const uint32_t* bh = &bhi[jj >> 1][(jj & 1) * 2];
                    const uint32_t* bl = &blo[jj >> 1][(jj & 1) * 2];
                    mma16816(acc[mi][jj], ahi[mi], bh);
                    mma16816(acc[mi][jj], ahi[mi], bl);
                    mma16816(acc[mi][jj], alo[mi], bh);
                }
        }

        if (hasNext) STORE_TILE(cur ^ 1);
        __syncthreads();
        cur ^= 1;
    }

    // ---- epilogue ----
    const int g = lane >> 2, t = lane & 3;
    if (flags & F_EXP) {
        float* rowst = (float*)smem;   // [128][NW*4] staging
        float rp[2][2] = {{0.f, 0.f}, {0.f, 0.f}};
        #pragma unroll
        for (int mi = 0; mi < 2; ++mi) {
            const long long r0 = m0 + wm0 + mi * 16 + g;
            const long long r1 = r0 + 8;
            float ai0 = 0.f, ai1 = 0.f;
            if (flags & F_ADDNORM) {
                ai0 = AddInv[ziAdd + r0] * addScale;
                ai1 = AddInv[ziAdd + r1] * addScale;
            }
            #pragma unroll
            for (int jj = 0; jj < 4; ++jj) {
                const int col = n0 + wn0 + jj * 8 + t * 2;
                float v00 = acc[mi][jj][0] * alpha, v01 = acc[mi][jj][1] * alpha;
                float v10 = acc[mi][jj][2] * alpha, v11 = acc[mi][jj][3] * alpha;
                if (Add) {
                    v00 += ai0 * Add[r0 * ldadd + col];
                    v01 += ai0 * Add[r0 * ldadd + col + 1];
                    v10 += ai1 * Add[r1 * ldadd + col];
                    v11 += ai1 * Add[r1 * ldadd + col + 1];
                }
                const float e00 = __expf(v00), e01 = __expf(v01);
                const float e10 = __expf(v10), e11 = __expf(v11);
                *(float2*)&C[r0 * ldc + col] = make_float2(e00, e01);
                *(float2*)&C[r1 * ldc + col] = make_float2(e10, e11);
                rp[0 + 0] [0] += 0.f; // (no-op to keep structure clear)
                rp[mi][0] += e00 + e01;
                rp[mi][1] += e10 + e11;
            }
        }
        const int cidx = (wid % NW) * 4 + t;
        rowst[(wm0 + g)      * (NW * 4) + cidx] = rp[0][0];
        rowst[(wm0 + g + 8)  * (NW * 4) + cidx] = rp[0][1];
        rowst[(wm0 + 16 + g) * (NW * 4) + cidx] = rp[1][0];
        rowst[(wm0 + 24 + g) * (NW * 4) + cidx] = rp[1][1];
        __syncthreads();
        if (tid < 128) {
            float s = 0.f;
            #pragma unroll
            for (int j = 0; j < NW * 4; ++j) s += rowst[tid * (NW * 4) + j];
            Psum[(ziP + m0 + tid) * 32 + blockIdx.x] = s;
        }
    } else {
        #pragma unroll
        for (int mi = 0; mi < 2; ++mi) {
            #pragma unroll
            for (int jj = 0; jj < 4; ++jj) {
                const long long r0 = m0 + wm0 + mi * 16 + g;
                const long long r1 = r0 + 8;
                const int col = n0 + wn0 + jj * 8 + t * 2;
                float v00 = acc[mi][jj][0] * alpha, v01 = acc[mi][jj][1] * alpha;
                float v10 = acc[mi][jj][2] * alpha, v11 = acc[mi][jj][3] * alpha;
                if (bias) { v00 += bias[col]; v01 += bias[col + 1];
                            v10 += bias[col]; v11 += bias[col + 1]; }
                if (Add) {
                    v00 += addScale * Add[r0 * ldadd + col];
                    v01 += addScale * Add[r0 * ldadd + col + 1];
                    v10 += addScale * Add[r1 * ldadd + col];
                    v11 += addScale * Add[r1 * ldadd + col + 1];
                }
                *(float2*)&C[r0 * ldc + col] = make_float2(v00, v01);
                *(float2*)&C[r1 * ldc + col] = make_float2(v10, v11);
            }
        }
    }
#undef LOAD_TILE
#undef STORE_TILE
}

// ---------------- row partial-sum reduction -> inverse ----------------
__global__ void __launch_bounds__(256) k_rowinv(
    const float* __restrict__ part, float* __restrict__ inv, int ncols)
{
    const int row = blockIdx.x * 8 + (threadIdx.x >> 5);
    const int lane = threadIdx.x & 31;
    float s = (lane < ncols) ? part[(long long)row * 32 + lane] : 0.f;
    #pragma unroll
    for (int o = 16; o; o >>= 1) s += __shfl_xor_sync(0xFFFFFFFFu, s, o);
    if (lane == 0) inv[row] = 1.0f / s;
}

// ---------------- residual + LayerNorm ----------------
__global__ void __launch_bounds__(256) k_ln_res(
    const float* __restrict__ xin, const float* __restrict__ hs,
    const float* __restrict__ g, const float* __restrict__ be,
    float* __restrict__ out)
{
    long long row = blockIdx.x;
    const float* xr = xin + row * H_;
    const float* hr = hs + row * H_;
    float* orow = out + row * H_;
    int tid = threadIdx.x;
    __shared__ float red[256];

    float v[4];
    float s = 0.0f;
    #pragma unroll
    for (int i = 0; i < 4; ++i) { v[i] = xr[tid + i * 256] + hr[tid + i * 256]; s += v[i]; }
    red[tid] = s; __syncthreads();
    for (int t = 128; t > 0; t >>= 1) {
        if (tid < t) red[tid] += red[tid + t];
        __syncthreads();
    }
    float mu = red[0] * (1.0f / H_); __syncthreads();

    float var = 0.0f;
    #pragma unroll
    for (int i = 0; i < 4; ++i) { float d = v[i] - mu; var += d * d; }
    red[tid] = var; __syncthreads();
    for (int t = 128; t > 0; t >>= 1) {
        if (tid < t) red[tid] += red[tid + t];
        __syncthreads();
    }
    float inv = rsqrtf(red[0] * (1.0f / H_) + 1e-12f);
    #pragma unroll
    for (int i = 0; i < 4; ++i) {
        int c = tid + i * 256;
        orow[c] = (v[i] - mu) * inv * g[c] + be[c];
    }
}

// ---------------- host-side launch helper ----------------
template<int BN>
static void launch_gemm(
    const float* A, const float* B, const float* bias, const float* Add,
    const float* AddInv, const float* AInv, float* C, float* Psum,
    int Mrows, int Ncols, int K, int lda, int ldb, int ldc, int ldadd,
    int Z, int zdiv,
    long long sA1, long long sA0, long long sB1, long long sB0,
    long long sC1, long long sC0, long long sAdd1, long long sAdd0,
    long long sAi1, long long sAi0, long long sNi1, long long sNi0,
    long long sP1, long long sP0,
    float alpha, float addScale, int flags)
{
    constexpr int BLK = (BN == 64) ? 256 : 512;
    constexpr int SMB = (BN == 64) ? (2 * 30720) : (2 * 40960);
    static bool attrSet = false;
    if (!attrSet) {
        cudaFuncSetAttribute((const void*)k_mma_gemm<BN, BLK>,
                             cudaFuncAttributeMaxDynamicSharedMemorySize, SMB);
        attrSet = true;
    }
    dim3 grid(Ncols / BN, Mrows / 128, Z);
    k_mma_gemm<BN, BLK><<<grid, BLK, SMB>>>(
        A, B, bias, Add, AddInv, AInv, C, Psum,
        K, lda, ldb, ldc, ldadd, zdiv,
        sA1, sA0, sB1, sB0, sC1, sC0, sAdd1, sAdd0,
        sAi1, sAi0, sNi1, sNi0, sP1, sP0,
        alpha, addScale, flags);
}

extern "C" void kernel_launch(void* const* d_in, const int* in_sizes, int n_in,
                              void* d_out, int out_size)
{
    const float* hs  = (const float*)d_in[0];
    const float* mc  = (const float*)d_in[1];
    const float* Wq  = (const float*)d_in[2];  const float* bq  = (const float*)d_in[3];
    const float* Wk  = (const float*)d_in[4];  const float* bk  = (const float*)d_in[5];
    const float* Wv  = (const float*)d_in[6];  const float* bv  = (const float*)d_in[7];
    const float* Wmq = (const float*)d_in[8];  const float* bmq = (const float*)d_in[9];
    const float* Wmk = (const float*)d_in[10]; const float* bmk = (const float*)d_in[11];
    const float* Wc  = (const float*)d_in[12]; const float* bc  = (const float*)d_in[13];
    const float* Wf  = (const float*)d_in[14]; const float* bf  = (const float*)d_in[15];
    const float* lg  = (const float*)d_in[16]; const float* lb  = (const float*)d_in[17];

    float* out   = (float*)d_out;                        // [B,S,H]
    float* probs = out + (long long)B_ * S_ * H_;        // [B,NH,S,S]

    float *q, *k, *v, *mq, *mk, *med, *cat, *x, *part, *minv, *pinv;
    cudaGetSymbolAddress((void**)&q,    g_q);
    cudaGetSymbolAddress((void**)&k,    g_k);
    cudaGetSymbolAddress((void**)&v,    g_v);
    cudaGetSymbolAddress((void**)&mq,   g_mq);
    cudaGetSymbolAddress((void**)&mk,   g_mk);
    cudaGetSymbolAddress((void**)&med,  g_med);
    cudaGetSymbolAddress((void**)&cat,  g_cat);
    cudaGetSymbolAddress((void**)&x,    g_x);
    cudaGetSymbolAddress((void**)&part, g_part);
    cudaGetSymbolAddress((void**)&minv, g_minv);
    cudaGetSymbolAddress((void**)&pinv, g_pinv);

    const int rows = B_ * S_;            // 4096
    const long long SS = (long long)S_ * S_;
    const long long SH = (long long)S_ * H_;
    const long long SM = (long long)S_ * M_;

    // Q, K, V projections (NN, BN=128)
    launch_gemm<128>(hs, Wq, bq, 0, 0, 0, q, 0, rows, H_, H_, H_, H_, H_, 0, 1, 1,
                0,0, 0,0, 0,0, 0,0, 0,0, 0,0, 0,0, 1.0f, 0.0f, 0);
    launch_gemm<128>(hs, Wk, bk, 0, 0, 0, k, 0, rows, H_, H_, H_, H_, H_, 0, 1, 1,
                0,0, 0,0, 0,0, 0,0, 0,0, 0,0, 0,0, 1.0f, 0.0f, 0);
    launch_gemm<128>(hs, Wv, bv, 0, 0, 0, v, 0, rows, H_, H_, H_, H_, H_, 0, 1, 1,
                0,0, 0,0, 0,0, 0,0, 0,0, 0,0, 0,0, 1.0f, 0.0f, 0);

    // medical projections (NN, BN=128)
    launch_gemm<128>(hs, Wmq, bmq, 0, 0, 0, mq, 0, rows, M_, H_, H_, M_, M_, 0, 1, 1,
                0,0, 0,0, 0,0, 0,0, 0,0, 0,0, 0,0, 1.0f, 0.0f, 0);
    launch_gemm<128>(mc, Wmk, bmk, 0, 0, 0, mk, 0, rows, M_, H_, H_, M_, M_, 0, 1, 1,
                0,0, 0,0, 0,0, 0,0, 0,0, 0,0, 0,0, 1.0f, 0.0f, 0);

    // med scores: exp(mq @ mk^T) -> g_med, partial row sums (NT, per batch, BN=128)
    launch_gemm<128>(mq, mk, 0, 0, 0, 0, med, part, S_, S_, M_, M_, M_, S_, 0, B_, 1,
                SM,0, SM,0, SS,0, 0,0, 0,0, 0,0, (long long)S_,0,
                1.0f, 0.0f, F_TRANS | F_EXP);
    k_rowinv<<<rows / 8, 256>>>(part, minv, S_ / 128);

    // attn scores: exp(qk/8 + 0.3*medexp*minv) -> probs, partial sums (NT, BN=128)
    launch_gemm<128>(q, k, 0, med, minv, 0, probs, part, S_, S_, D_, H_, H_, S_, S_,
                B_ * NH_, NH_,
                SH, D_, SH, D_, NH_ * SS, SS, SS, 0,
                (long long)S_, 0, 0, 0,
                (long long)NH_ * S_, (long long)S_,
                0.125f, 0.3f, F_TRANS | F_EXP | F_ADDNORM);
    k_rowinv<<<(B_ * NH_ * S_) / 8, 256>>>(part, pinv, S_ / 128);

    // ctx = (probs * pinv) @ v -> cat[:, 0:1024]; normalized probs written back (NN, BN=64)
    launch_gemm<64>(probs, v, 0, 0, 0, pinv, cat, 0, S_, D_, S_, S_, H_, CAT_, 0,
                B_ * NH_, NH_,
                NH_ * SS, SS, SH, D_, (long long)S_ * CAT_, D_, 0, 0,
                0,0, (long long)NH_ * S_, (long long)S_, 0,0,
                1.0f, 0.0f, F_NORMA);

    // clin = ctx @ Wc + bc -> cat[:, 1024:1536]  (NN, BN=128)
    launch_gemm<128>(cat, Wc, bc, 0, 0, 0, cat + H_, 0, rows, M_, H_, CAT_, M_, CAT_, 0, 1, 1,
                0,0, 0,0, 0,0, 0,0, 0,0, 0,0, 0,0, 1.0f, 0.0f, 0);

    // final = cat @ Wf + bf  (NN, BN=128)
    launch_gemm<128>(cat, Wf, bf, 0, 0, 0, x, 0, rows, H_, CAT_, CAT_, H_, H_, 0, 1, 1,
                0,0, 0,0, 0,0, 0,0, 0,0, 0,0, 0,0, 1.0f, 0.0f, 0);

    // residual + layernorm -> out
    k_ln_res<<<rows, 256>>>(x, hs, lg, lb, out);
}

// round 9
// speedup vs baseline: 1.0007x; 1.0007x over previous
#include <cuda_runtime.h>
#include <cuda_bf16.h>
#include <cstdint>

// Shapes (fixed by the problem)
#define B_   2
#define S_   2048
#define H_   1024
#define NH_  16
#define M_   512
#define D_   64
#define CAT_ (H_ + M_)   // 1536

// ---------------- scratch (static device memory; no allocations allowed) ---
__device__ float g_q  [(long long)B_*S_*H_];
__device__ float g_k  [(long long)B_*S_*H_];
__device__ float g_v  [(long long)B_*S_*H_];
__device__ float g_mq [(long long)B_*S_*M_];
__device__ float g_mk [(long long)B_*S_*M_];
__device__ float g_med[(long long)B_*S_*S_];
__device__ float g_cat[(long long)B_*S_*CAT_];
__device__ float g_x  [(long long)B_*S_*H_];
__device__ float g_part[(long long)B_*NH_*S_*32];   // per-tile row partial sums
__device__ float g_minv[(long long)B_*S_];          // med row inv sums
__device__ float g_pinv[(long long)B_*NH_*S_];      // probs row inv sums

// ---------------- helpers ----------------
__device__ __forceinline__ uint32_t smem_to_u32(const void* p) {
    uint32_t a;
    asm("{ .reg .u64 t; cvta.to.shared.u64 t, %1; cvt.u32.u64 %0, t; }" : "=r"(a) : "l"(p));
    return a;
}
__device__ __forceinline__ void ldmx4(uint32_t* r, uint32_t addr) {
    asm volatile("ldmatrix.sync.aligned.m8n8.x4.shared.b16 {%0,%1,%2,%3}, [%4];"
        : "=r"(r[0]), "=r"(r[1]), "=r"(r[2]), "=r"(r[3]) : "r"(addr));
}
__device__ __forceinline__ void ldmx4t(uint32_t* r, uint32_t addr) {
    asm volatile("ldmatrix.sync.aligned.m8n8.x4.trans.shared.b16 {%0,%1,%2,%3}, [%4];"
        : "=r"(r[0]), "=r"(r[1]), "=r"(r[2]), "=r"(r[3]) : "r"(addr));
}
__device__ __forceinline__ void mma16816(float* d, const uint32_t* a, const uint32_t* b) {
    asm volatile(
        "mma.sync.aligned.m16n8k16.row.col.f32.bf16.bf16.f32 "
        "{%0,%1,%2,%3}, {%4,%5,%6,%7}, {%8,%9}, {%0,%1,%2,%3};"
        : "+f"(d[0]), "+f"(d[1]), "+f"(d[2]), "+f"(d[3])
        : "r"(a[0]), "r"(a[1]), "r"(a[2]), "r"(a[3]), "r"(b[0]), "r"(b[1]));
}

struct alignas(16) BF8 { __nv_bfloat16 v[8]; };
__device__ __forceinline__ void split8(const float* f, BF8& hi, BF8& lo) {
    #pragma unroll
    for (int i = 0; i < 8; ++i) {
        __nv_bfloat16 h = __float2bfloat16(f[i]);
        hi.v[i] = h;
        lo.v[i] = __float2bfloat16(f[i] - __bfloat162float(h));
    }
}

// epilogue/flag bits
#define F_TRANS   1
#define F_EXP     2
#define F_ADDNORM 4
#define F_NORMA   8

#define A_STRIDE_B 80
#define BNT_STRIDE_B 80

// ---------------- universal pipelined bf16-split mma.sync GEMM ----------------
// BM=128 fixed; BN template (64: 256 thr / 8 warps, 128: 512 thr / 16 warps).
// C[M,N] = alpha * A[M,K] @ op(B) (+bias[col]) (+addScale*Add[row,col]*AddInv[row])
// F_EXP: C = exp(val); per-row tile partial sums -> Psum[(zP+row)*32 + bx]
// F_NORMA: A rows scaled by AInv[zNi+row] during load AND written back to gmem.
template<int BN, int BLK>
__global__ void __launch_bounds__(BLK, (BN == 64) ? 2 : 1) k_mma_gemm(
    const float* __restrict__ A, const float* __restrict__ B,
    const float* __restrict__ bias, const float* __restrict__ Add,
    const float* __restrict__ AddInv, const float* __restrict__ AInv,
    float* __restrict__ C, float* __restrict__ Psum,
    int K, int lda, int ldb, int ldc, int ldadd, int zdiv,
    long long sA1, long long sA0, long long sB1, long long sB0,
    long long sC1, long long sC0, long long sAdd1, long long sAdd0,
    long long sAi1, long long sAi0, long long sNi1, long long sNi0,
    long long sP1, long long sP0,
    float alpha, float addScale, int flags)
{
    constexpr int NW      = BN / 32;              // n-warps
    constexpr int BNN_ST  = (BN == 64) ? 144 : 272;
    constexpr int BSZ     = (BN == 64) ? 5120 : 10240;
    constexpr int OFF_BHI = 20480;
    constexpr int OFF_BLO = 20480 + BSZ;
    constexpr int STAGE   = 20480 + 2 * BSZ;
    constexpr int APT     = 4096 / BLK;           // A floats per thread (16 / 8)
    constexpr int CPR     = 32 / APT;             // A chunks per row (2 / 4)
    constexpr int NCPR    = BN / 8;               // B-NN chunks per row

    extern __shared__ __align__(16) uint8_t smem[];
    const uint32_t sb = smem_to_u32(smem);

    const int tid = threadIdx.x;
    const int wid = tid >> 5;
    const int lane = tid & 31;

    const int z = blockIdx.z;
    const int z1 = z / zdiv, z0 = z % zdiv;
    A += z1 * sA1 + z0 * sA0;
    B += z1 * sB1 + z0 * sB0;
    C += z1 * sC1 + z0 * sC0;
    if (Add) Add += z1 * sAdd1 + z0 * sAdd0;
    const long long ziAdd = z1 * sAi1 + z0 * sAi0;
    const long long ziN   = z1 * sNi1 + z0 * sNi0;
    const long long ziP   = z1 * sP1  + z0 * sP0;

    const int m0 = blockIdx.y * 128;
    const int n0 = blockIdx.x * BN;

    const int wm0 = (wid / NW) * 32;
    const int wn0 = (wid % NW) * 32;

    // ldmatrix per-lane offsets (within one stage buffer)
    const uint32_t aLane = (uint32_t)(wm0 + (lane & 15)) * A_STRIDE_B + ((lane >> 4) << 3) * 2;
    const uint32_t bLaneNT = (uint32_t)(wn0 + ((lane >> 1) & 8) + (lane & 7)) * BNT_STRIDE_B
                           + (uint32_t)(lane & 8) * 2;
    const uint32_t bLaneNN = (uint32_t)(lane & 15) * BNN_ST
                           + (uint32_t)(wn0 + ((lane >> 1) & 8)) * 2;

    // global-load coords
    const int ar = tid / CPR, ac = (tid % CPR) * APT;  // A
    const int ntr = tid >> 2, ntk = (tid & 3) * 8;     // B NT: BLK/4 rows (== BN)
    const int nnr = tid / NCPR, nnc = (tid % NCPR) * 8; // B NN: 32 rows

    const float aScale = (flags & F_NORMA) ? AInv[ziN + m0 + ar] : 1.0f;

    float acc[2][4][4];
    #pragma unroll
    for (int i = 0; i < 2; ++i)
        #pragma unroll
        for (int j = 0; j < 4; ++j)
            #pragma unroll
            for (int e = 0; e < 4; ++e) acc[i][j][e] = 0.0f;

    float fA[APT], fB[8];

#define LOAD_TILE(k0v) {                                                            \
        const float* srcA = A + (long long)(m0 + ar) * lda + (k0v) + ac;            \
        _Pragma("unroll") for (int e = 0; e < APT; e += 4)                          \
            *(float4*)(fA + e) = *(const float4*)(srcA + e);                        \
        if (flags & F_NORMA) {                                                      \
            _Pragma("unroll") for (int e = 0; e < APT; ++e) fA[e] *= aScale;        \
            float* wb = const_cast<float*>(srcA);                                   \
            _Pragma("unroll") for (int e = 0; e < APT; e += 4)                      \
                *(float4*)(wb + e) = *(float4*)(fA + e);                            \
        }                                                                           \
        if (flags & F_TRANS) {                                                      \
            const float* srcB = B + (long long)(n0 + ntr) * ldb + (k0v) + ntk;      \
            *(float4*)(fB)     = *(const float4*)(srcB);                            \
            *(float4*)(fB + 4) = *(const float4*)(srcB + 4);                        \
        } else {                                                                    \
            const float* srcB = B + (long long)((k0v) + nnr) * ldb + n0 + nnc;      \
            *(float4*)(fB)     = *(const float4*)(srcB);                            \
            *(float4*)(fB + 4) = *(const float4*)(srcB + 4);                        \
        }                                                                           \
    }

#define STORE_TILE(st) {                                                            \
        uint8_t* sp = smem + (st) * STAGE;                                          \
        _Pragma("unroll") for (int gg = 0; gg < APT / 8; ++gg) {                    \
            BF8 h, l; split8(fA + gg * 8, h, l);                                    \
            const uint32_t offA = (uint32_t)ar * A_STRIDE_B + (ac + gg * 8) * 2;    \
            *(uint4*)(sp + 0     + offA) = *(const uint4*)&h;                       \
            *(uint4*)(sp + 10240 + offA) = *(const uint4*)&l;                       \
        }                                                                           \
        BF8 hb, lb2; split8(fB, hb, lb2);                                           \
        const uint32_t offB = (flags & F_TRANS)                                     \
            ? (uint32_t)ntr * BNT_STRIDE_B + ntk * 2                                \
            : (uint32_t)nnr * BNN_ST + nnc * 2;                                     \
        *(uint4*)(sp + OFF_BHI + offB) = *(const uint4*)&hb;                        \
        *(uint4*)(sp + OFF_BLO + offB) = *(const uint4*)&lb2;                       \
    }

    const int nIter = K >> 5;   // BK = 32

    LOAD_TILE(0);
    STORE_TILE(0);
    __syncthreads();

    int cur = 0;
    for (int it = 0; it < nIter; ++it) {
        const bool hasNext = (it + 1 < nIter);
        if (hasNext) LOAD_TILE((it + 1) << 5);

        const uint32_t stb = sb + cur * STAGE;
        #pragma unroll
        for (int kk = 0; kk < 2; ++kk) {
            uint32_t ahi[2][4], alo[2][4], bhi[2][4], blo[2][4];
            const uint32_t akk = aLane + (uint32_t)(kk * 16) * 2;
            #pragma unroll
            for (int mi = 0; mi < 2; ++mi) {
                const uint32_t off = akk + (uint32_t)(mi * 16) * A_STRIDE_B;
                ldmx4(ahi[mi], stb + 0 + off);
                ldmx4(alo[mi], stb + 10240 + off);
            }
            if (flags & F_TRANS) {
                const uint32_t bkk = bLaneNT + (uint32_t)(kk * 16) * 2;
                #pragma unroll
                for (int nj = 0; nj < 2; ++nj) {
                    const uint32_t off = bkk + (uint32_t)(nj * 16) * BNT_STRIDE_B;
                    ldmx4(bhi[nj], stb + OFF_BHI + off);
                    ldmx4(blo[nj], stb + OFF_BLO + off);
                }
            } else {
                const uint32_t bkk = bLaneNN + (uint32_t)(kk * 16) * BNN_ST;
                #pragma unroll
                for (int nj = 0; nj < 2; ++nj) {
                    const uint32_t off = bkk + (uint32_t)(nj * 16) * 2;
                    ldmx4t(bhi[nj], stb + OFF_BHI + off);
                    ldmx4t(blo[nj], stb + OFF_BLO + off);
                }
            }
            #pragma unroll
            for (int mi = 0; mi < 2; ++mi)
                #pragma unroll
                for (int jj = 0; jj < 4; ++jj) {
                    const uint32_t* bh = &bhi[jj >> 1][(jj & 1) * 2];
                    const uint32_t* bl = &blo[jj >> 1][(jj & 1) * 2];
                    mma16816(acc[mi][jj], ahi[mi], bh);
                    mma16816(acc[mi][jj], ahi[mi], bl);
                    mma16816(acc[mi][jj], alo[mi], bh);
                }
        }

        if (hasNext) STORE_TILE(cur ^ 1);
        __syncthreads();
        cur ^= 1;
    }

    // ---- epilogue ----
    const int g = lane >> 2, t = lane & 3;
    if (flags & F_EXP) {
        float* rowst = (float*)smem;   // [128][NW*4] staging
        float rp[2][2] = {{0.f, 0.f}, {0.f, 0.f}};
        #pragma unroll
        for (int mi = 0; mi < 2; ++mi) {
            const long long r0 = m0 + wm0 + mi * 16 + g;
            const long long r1 = r0 + 8;
            float ai0 = 0.f, ai1 = 0.f;
            if (flags & F_ADDNORM) {
                ai0 = AddInv[ziAdd + r0] * addScale;
                ai1 = AddInv[ziAdd + r1] * addScale;
            }
            #pragma unroll
            for (int jj = 0; jj < 4; ++jj) {
                const int col = n0 + wn0 + jj * 8 + t * 2;
                float v00 = acc[mi][jj][0] * alpha, v01 = acc[mi][jj][1] * alpha;
                float v10 = acc[mi][jj][2] * alpha, v11 = acc[mi][jj][3] * alpha;
                if (Add) {
                    v00 += ai0 * Add[r0 * ldadd + col];
                    v01 += ai0 * Add[r0 * ldadd + col + 1];
                    v10 += ai1 * Add[r1 * ldadd + col];
                    v11 += ai1 * Add[r1 * ldadd + col + 1];
                }
                const float e00 = __expf(v00), e01 = __expf(v01);
                const float e10 = __expf(v10), e11 = __expf(v11);
                *(float2*)&C[r0 * ldc + col] = make_float2(e00, e01);
                *(float2*)&C[r1 * ldc + col] = make_float2(e10, e11);
                rp[0 + 0] [0] += 0.f; // (no-op to keep structure clear)
                rp[mi][0] += e00 + e01;
                rp[mi][1] += e10 + e11;
            }
        }
        const int cidx = (wid % NW) * 4 + t;
        rowst[(wm0 + g)      * (NW * 4) + cidx] = rp[0][0];
        rowst[(wm0 + g + 8)  * (NW * 4) + cidx] = rp[0][1];
        rowst[(wm0 + 16 + g) * (NW * 4) + cidx] = rp[1][0];
        rowst[(wm0 + 24 + g) * (NW * 4) + cidx] = rp[1][1];
        __syncthreads();
        if (tid < 128) {
            float s = 0.f;
            #pragma unroll
            for (int j = 0; j < NW * 4; ++j) s += rowst[tid * (NW * 4) + j];
            Psum[(ziP + m0 + tid) * 32 + blockIdx.x] = s;
        }
    } else {
        #pragma unroll
        for (int mi = 0; mi < 2; ++mi) {
            #pragma unroll
            for (int jj = 0; jj < 4; ++jj) {
                const long long r0 = m0 + wm0 + mi * 16 + g;
                const long long r1 = r0 + 8;
                const int col = n0 + wn0 + jj * 8 + t * 2;
                float v00 = acc[mi][jj][0] * alpha, v01 = acc[mi][jj][1] * alpha;
                float v10 = acc[mi][jj][2] * alpha, v11 = acc[mi][jj][3] * alpha;
                if (bias) { v00 += bias[col]; v01 += bias[col + 1];
                            v10 += bias[col]; v11 += bias[col + 1]; }
                if (Add) {
                    v00 += addScale * Add[r0 * ldadd + col];
                    v01 += addScale * Add[r0 * ldadd + col + 1];
                    v10 += addScale * Add[r1 * ldadd + col];
                    v11 += addScale * Add[r1 * ldadd + col + 1];
                }
                *(float2*)&C[r0 * ldc + col] = make_float2(v00, v01);
                *(float2*)&C[r1 * ldc + col] = make_float2(v10, v11);
            }
        }
    }
#undef LOAD_TILE
#undef STORE_TILE
}

// ---------------- row partial-sum reduction -> inverse ----------------
__global__ void __launch_bounds__(256) k_rowinv(
    const float* __restrict__ part, float* __restrict__ inv, int ncols)
{
    const int row = blockIdx.x * 8 + (threadIdx.x >> 5);
    const int lane = threadIdx.x & 31;
    float s = (lane < ncols) ? part[(long long)row * 32 + lane] : 0.f;
    #pragma unroll
    for (int o = 16; o; o >>= 1) s += __shfl_xor_sync(0xFFFFFFFFu, s, o);
    if (lane == 0) inv[row] = 1.0f / s;
}

// ---------------- residual + LayerNorm ----------------
__global__ void __launch_bounds__(256) k_ln_res(
    const float* __restrict__ xin, const float* __restrict__ hs,
    const float* __restrict__ g, const float* __restrict__ be,
    float* __restrict__ out)
{
    long long row = blockIdx.x;
    const float* xr = xin + row * H_;
    const float* hr = hs + row * H_;
    float* orow = out + row * H_;
    int tid = threadIdx.x;
    __shared__ float red[256];

    float v[4];
    float s = 0.0f;
    #pragma unroll
    for (int i = 0; i < 4; ++i) { v[i] = xr[tid + i * 256] + hr[tid + i * 256]; s += v[i]; }
    red[tid] = s; __syncthreads();
    for (int t = 128; t > 0; t >>= 1) {
        if (tid < t) red[tid] += red[tid + t];
        __syncthreads();
    }
    float mu = red[0] * (1.0f / H_); __syncthreads();

    float var = 0.0f;
    #pragma unroll
    for (int i = 0; i < 4; ++i) { float d = v[i] - mu; var += d * d; }
    red[tid] = var; __syncthreads();
    for (int t = 128; t > 0; t >>= 1) {
        if (tid < t) red[tid] += red[tid + t];
        __syncthreads();
    }
    float inv = rsqrtf(red[0] * (1.0f / H_) + 1e-12f);
    #pragma unroll
    for (int i = 0; i < 4; ++i) {
        int c = tid + i * 256;
        orow[c] = (v[i] - mu) * inv * g[c] + be[c];
    }
}

// ---------------- host-side launch helper ----------------
template<int BN>
static void launch_gemm(
    const float* A, const float* B, const float* bias, const float* Add,
    const float* AddInv, const float* AInv, float* C, float* Psum,
    int Mrows, int Ncols, int K, int lda, int ldb, int ldc, int ldadd,
    int Z, int zdiv,
    long long sA1, long long sA0, long long sB1, long long sB0,
    long long sC1, long long sC0, long long sAdd1, long long sAdd0,
    long long sAi1, long long sAi0, long long sNi1, long long sNi0,
    long long sP1, long long sP0,
    float alpha, float addScale, int flags)
{
    constexpr int BLK = (BN == 64) ? 256 : 512;
    constexpr int SMB = (BN == 64) ? (2 * 30720) : (2 * 40960);
    static bool attrSet = false;
    if (!attrSet) {
        cudaFuncSetAttribute((const void*)k_mma_gemm<BN, BLK>,
                             cudaFuncAttributeMaxDynamicSharedMemorySize, SMB);
        attrSet = true;
    }
    dim3 grid(Ncols / BN, Mrows / 128, Z);
    k_mma_gemm<BN, BLK><<<grid, BLK, SMB>>>(
        A, B, bias, Add, AddInv, AInv, C, Psum,
        K, lda, ldb, ldc, ldadd, zdiv,
        sA1, sA0, sB1, sB0, sC1, sC0, sAdd1, sAdd0,
        sAi1, sAi0, sNi1, sNi0, sP1, sP0,
        alpha, addScale, flags);
}

extern "C" void kernel_launch(void* const* d_in, const int* in_sizes, int n_in,
                              void* d_out, int out_size)
{
    const float* hs  = (const float*)d_in[0];
    const float* mc  = (const float*)d_in[1];
    const float* Wq  = (const float*)d_in[2];  const float* bq  = (const float*)d_in[3];
    const float* Wk  = (const float*)d_in[4];  const float* bk  = (const float*)d_in[5];
    const float* Wv  = (const float*)d_in[6];  const float* bv  = (const float*)d_in[7];
    const float* Wmq = (const float*)d_in[8];  const float* bmq = (const float*)d_in[9];
    const float* Wmk = (const float*)d_in[10]; const float* bmk = (const float*)d_in[11];
    const float* Wc  = (const float*)d_in[12]; const float* bc  = (const float*)d_in[13];
    const float* Wf  = (const float*)d_in[14]; const float* bf  = (const float*)d_in[15];
    const float* lg  = (const float*)d_in[16]; const float* lb  = (const float*)d_in[17];

    float* out   = (float*)d_out;                        // [B,S,H]
    float* probs = out + (long long)B_ * S_ * H_;        // [B,NH,S,S]

    float *q, *k, *v, *mq, *mk, *med, *cat, *x, *part, *minv, *pinv;
    cudaGetSymbolAddress((void**)&q,    g_q);
    cudaGetSymbolAddress((void**)&k,    g_k);
    cudaGetSymbolAddress((void**)&v,    g_v);
    cudaGetSymbolAddress((void**)&mq,   g_mq);
    cudaGetSymbolAddress((void**)&mk,   g_mk);
    cudaGetSymbolAddress((void**)&med,  g_med);
    cudaGetSymbolAddress((void**)&cat,  g_cat);
    cudaGetSymbolAddress((void**)&x,    g_x);
    cudaGetSymbolAddress((void**)&part, g_part);
    cudaGetSymbolAddress((void**)&minv, g_minv);
    cudaGetSymbolAddress((void**)&pinv, g_pinv);

    const int rows = B_ * S_;            // 4096
    const long long SS = (long long)S_ * S_;
    const long long SH = (long long)S_ * H_;
    const long long SM = (long long)S_ * M_;

    // Q, K, V projections (NN, BN=128)
    launch_gemm<128>(hs, Wq, bq, 0, 0, 0, q, 0, rows, H_, H_, H_, H_, H_, 0, 1, 1,
                0,0, 0,0, 0,0, 0,0, 0,0, 0,0, 0,0, 1.0f, 0.0f, 0);
    launch_gemm<128>(hs, Wk, bk, 0, 0, 0, k, 0, rows, H_, H_, H_, H_, H_, 0, 1, 1,
                0,0, 0,0, 0,0, 0,0, 0,0, 0,0, 0,0, 1.0f, 0.0f, 0);
    launch_gemm<128>(hs, Wv, bv, 0, 0, 0, v, 0, rows, H_, H_, H_, H_, H_, 0, 1, 1,
                0,0, 0,0, 0,0, 0,0, 0,0, 0,0, 0,0, 1.0f, 0.0f, 0);

    // medical projections (NN, BN=128)
    launch_gemm<128>(hs, Wmq, bmq, 0, 0, 0, mq, 0, rows, M_, H_, H_, M_, M_, 0, 1, 1,
                0,0, 0,0, 0,0, 0,0, 0,0, 0,0, 0,0, 1.0f, 0.0f, 0);
    launch_gemm<128>(mc, Wmk, bmk, 0, 0, 0, mk, 0, rows, M_, H_, H_, M_, M_, 0, 1, 1,
                0,0, 0,0, 0,0, 0,0, 0,0, 0,0, 0,0, 1.0f, 0.0f, 0);

    // med scores: exp(mq @ mk^T) -> g_med, partial row sums (NT, per batch, BN=128)
    launch_gemm<128>(mq, mk, 0, 0, 0, 0, med, part, S_, S_, M_, M_, M_, S_, 0, B_, 1,
                SM,0, SM,0, SS,0, 0,0, 0,0, 0,0, (long long)S_,0,
                1.0f, 0.0f, F_TRANS | F_EXP);
    k_rowinv<<<rows / 8, 256>>>(part, minv, S_ / 128);

    // attn scores: exp(qk/8 + 0.3*medexp*minv) -> probs, partial sums (NT, BN=128)
    launch_gemm<128>(q, k, 0, med, minv, 0, probs, part, S_, S_, D_, H_, H_, S_, S_,
                B_ * NH_, NH_,
                SH, D_, SH, D_, NH_ * SS, SS, SS, 0,
                (long long)S_, 0, 0, 0,
                (long long)NH_ * S_, (long long)S_,
                0.125f, 0.3f, F_TRANS | F_EXP | F_ADDNORM);
    k_rowinv<<<(B_ * NH_ * S_) / 8, 256>>>(part, pinv, S_ / 128);

    // ctx = (probs * pinv) @ v -> cat[:, 0:1024]; normalized probs written back (NN, BN=64)
    launch_gemm<64>(probs, v, 0, 0, 0, pinv, cat, 0, S_, D_, S_, S_, H_, CAT_, 0,
                B_ * NH_, NH_,
                NH_ * SS, SS, SH, D_, (long long)S_ * CAT_, D_, 0, 0,
                0,0, (long long)NH_ * S_, (long long)S_, 0,0,
                1.0f, 0.0f, F_NORMA);

    // clin = ctx @ Wc + bc -> cat[:, 1024:1536]  (NN, BN=128)
    launch_gemm<128>(cat, Wc, bc, 0, 0, 0, cat + H_, 0, rows, M_, H_, CAT_, M_, CAT_, 0, 1, 1,
                0,0, 0,0, 0,0, 0,0, 0,0, 0,0, 0,0, 1.0f, 0.0f, 0);

    // final = cat @ Wf + bf  (NN, BN=128)
    launch_gemm<128>(cat, Wf, bf, 0, 0, 0, x, 0, rows, H_, CAT_, CAT_, H_, H_, 0, 1, 1,
                0,0, 0,0, 0,0, 0,0, 0,0, 0,0, 0,0, 1.0f, 0.0f, 0);

    // residual + layernorm -> out
    k_ln_res<<<rows, 256>>>(x, hs, lg, lb, out);
}

// round 14
// speedup vs baseline: 1.0265x; 1.0258x over previous
#include <cuda_runtime.h>
#include <cuda_bf16.h>
#include <cstdint>
typedef __nv_bfloat16 bf16;
typedef long long ll;

#define B_ 2
#define S_ 2048
#define H_ 1024
#define NH_ 16
#define M_ 512

// ---------- static scratch ----------
__device__ __align__(16) bf16 g_inH [8388608], g_inL [8388608];   // hs|mc pairs
__device__ __align__(16) bf16 g_wH  [3145728], g_wL  [3145728];   // Wq|Wk|Wv
__device__ __align__(16) bf16 g_wmH [1048576], g_wmL [1048576];   // Wmq|Wmk
__device__ __align__(16) bf16 g_wcH [524288],  g_wcL [524288];
__device__ __align__(16) bf16 g_wfH [1572864], g_wfL [1572864];
__device__ float g_b3 [3072];
__device__ float g_bm2[1024];
__device__ __align__(16) bf16 g_qkvH[12582912], g_qkvL[12582912]; // q|k|v pairs
__device__ __align__(16) bf16 g_mqkH[4194304],  g_mqkL[4194304];  // mq|mk pairs
__device__ float g_med [8388608];                                  // exp med scores
__device__ __align__(16) bf16 g_catH[6291456],  g_catL[6291456];  // cat pair [4096][1536]
__device__ float g_x   [4194304];
__device__ float g_part[2097152];
__device__ float g_minv[4096];
__device__ float g_pinv[65536];

// ---------- helpers ----------
__device__ __forceinline__ uint32_t smem_to_u32(const void* p) {
    uint32_t a;
    asm("{ .reg .u64 t; cvta.to.shared.u64 t, %1; cvt.u32.u64 %0, t; }" : "=r"(a) : "l"(p));
    return a;
}
__device__ __forceinline__ void ldmx4(uint32_t* r, uint32_t a) {
    asm volatile("ldmatrix.sync.aligned.m8n8.x4.shared.b16 {%0,%1,%2,%3}, [%4];"
        : "=r"(r[0]), "=r"(r[1]), "=r"(r[2]), "=r"(r[3]) : "r"(a));
}
__device__ __forceinline__ void ldmx4t(uint32_t* r, uint32_t a) {
    asm volatile("ldmatrix.sync.aligned.m8n8.x4.trans.shared.b16 {%0,%1,%2,%3}, [%4];"
        : "=r"(r[0]), "=r"(r[1]), "=r"(r[2]), "=r"(r[3]) : "r"(a));
}
__device__ __forceinline__ void mma16816(float* d, const uint32_t* a, const uint32_t* b) {
    asm volatile(
        "mma.sync.aligned.m16n8k16.row.col.f32.bf16.bf16.f32 "
        "{%0,%1,%2,%3}, {%4,%5,%6,%7}, {%8,%9}, {%0,%1,%2,%3};"
        : "+f"(d[0]), "+f"(d[1]), "+f"(d[2]), "+f"(d[3])
        : "r"(a[0]), "r"(a[1]), "r"(a[2]), "r"(a[3]), "r"(b[0]), "r"(b[1]));
}
__device__ __forceinline__ void cp16(uint32_t dst, const void* src) {
    asm volatile("cp.async.cg.shared.global [%0], [%1], 16;" :: "r"(dst), "l"(src));
}
#define CP_COMMIT() asm volatile("cp.async.commit_group;")
#define CP_WAIT1()  asm volatile("cp.async.wait_group 1;")
#define CP_WAIT0()  asm volatile("cp.async.wait_group 0;")

struct alignas(16) BF8 { bf16 v[8]; };
__device__ __forceinline__ void split8(const float* f, BF8& hi, BF8& lo) {
    #pragma unroll
    for (int i = 0; i < 8; ++i) {
        bf16 h = __float2bfloat16(f[i]);
        hi.v[i] = h;
        lo.v[i] = __float2bfloat16(f[i] - __bfloat162float(h));
    }
}
__device__ __forceinline__ void split_store2(bf16* H, bf16* L, ll idx, float a, float b) {
    __nv_bfloat162 h, l;
    h.x = __float2bfloat16(a); h.y = __float2bfloat16(b);
    l.x = __float2bfloat16(a - __bfloat162float(h.x));
    l.y = __float2bfloat16(b - __bfloat162float(h.y));
    *(__nv_bfloat162*)(H + idx) = h;
    *(__nv_bfloat162*)(L + idx) = l;
}

#define F_TRANS   1
#define F_EXP     2
#define F_ADDNORM 4
#define F_OUTPAIR 8

// ---------- split prepass ----------
__global__ void __launch_bounds__(256) k_split(const float* s, bf16* h, bf16* l, int n8) {
    for (int i = blockIdx.x * 256 + threadIdx.x; i < n8; i += gridDim.x * 256) {
        float f[8];
        *(float4*)(f)     = *(const float4*)(s + (ll)i * 8);
        *(float4*)(f + 4) = *(const float4*)(s + (ll)i * 8 + 4);
        BF8 hi, lo; split8(f, hi, lo);
        *(uint4*)(h + (ll)i * 8) = *(const uint4*)&hi;
        *(uint4*)(l + (ll)i * 8) = *(const uint4*)&lo;
    }
}
__global__ void __launch_bounds__(1024) k_pack_bias(
    const float* bq, const float* bk, const float* bv,
    const float* bmq, const float* bmk)
{
    int t = threadIdx.x;
    g_b3[t] = bq[t]; g_b3[1024 + t] = bk[t]; g_b3[2048 + t] = bv[t];
    if (t < 512) { g_bm2[t] = bmq[t]; g_bm2[512 + t] = bmk[t]; }
}

// ---------- cp.async 3-stage pre-split GEMM: CTA 128x128, 512 thr ----------
// stage: AH 0, AL 10240, BH 20480, BL 30720; stage=40960, x3 = 122880 B
__global__ void __launch_bounds__(512, 1) k_ps(
    const bf16* __restrict__ AH, const bf16* __restrict__ AL,
    const bf16* __restrict__ BH, const bf16* __restrict__ BL,
    const float* __restrict__ bias, const float* __restrict__ Add,
    const float* __restrict__ AddInv,
    float* __restrict__ C, bf16* __restrict__ CH, bf16* __restrict__ CL,
    float* __restrict__ Psum,
    int K, int lda, int ldb, int ldc, int ldadd, int zdiv,
    ll sA1, ll sA0, ll sB1, ll sB0, ll sC1, ll sC0,
    ll sAdd1, ll sAdd0, ll sAi1, ll sAi0, ll sP1, ll sP0, ll sBias1,
    float alpha, float addScale, int flags)
{
    extern __shared__ __align__(16) uint8_t smem[];
    const uint32_t sb = smem_to_u32(smem);
    const int tid = threadIdx.x, wid = tid >> 5, lane = tid & 31;
    const int z = blockIdx.z, z1 = z / zdiv, z0 = z % zdiv;
    AH += z1 * sA1 + z0 * sA0;  AL += z1 * sA1 + z0 * sA0;
    BH += z1 * sB1 + z0 * sB0;  BL += z1 * sB1 + z0 * sB0;
    const ll cBase = z1 * sC1 + z0 * sC0;
    const ll ziAdd = z1 * sAdd1 + z0 * sAdd0;
    const ll ziAi  = z1 * sAi1 + z0 * sAi0;
    const ll ziP   = z1 * sP1 + z0 * sP0;
    const ll ziB   = z1 * sBias1;

    const int m0 = blockIdx.y * 128, n0 = blockIdx.x * 128;
    const int wm0 = (wid >> 2) * 32, wn0 = (wid & 3) * 32;

    const uint32_t aLane = (uint32_t)(wm0 + (lane & 15)) * 80u + (uint32_t)(lane >> 4) * 16u;
    const uint32_t bLaneNT = (uint32_t)(wn0 + ((lane >> 1) & 8) + (lane & 7)) * 80u
                           + (uint32_t)(lane & 8) * 2u;
    const uint32_t bLaneNN = (uint32_t)(lane & 15) * 272u
                           + (uint32_t)(wn0 + ((lane >> 1) & 8)) * 2u;

    const int arow = tid >> 2, akc = tid & 3;   // A: 128 rows x 4x16B
    const int bkr  = tid >> 4, bnc = tid & 15;  // B NN: 32 rows x 16x16B

    float acc[2][4][4];
    #pragma unroll
    for (int i = 0; i < 2; ++i)
        #pragma unroll
        for (int j = 0; j < 4; ++j)
            #pragma unroll
            for (int e = 0; e < 4; ++e) acc[i][j][e] = 0.0f;

#define ISSUE(itv) { \
        const int k0i = (itv) << 5; \
        const uint32_t st = sb + (uint32_t)((itv) % 3) * 40960u; \
        const ll aIdx = (ll)(m0 + arow) * lda + k0i + akc * 8; \
        cp16(st + (uint32_t)arow * 80u + (uint32_t)akc * 16u, AH + aIdx); \
        cp16(st + 10240u + (uint32_t)arow * 80u + (uint32_t)akc * 16u, AL + aIdx); \
        if (flags & F_TRANS) { \
            const ll bIdx = (ll)(n0 + arow) * ldb + k0i + akc * 8; \
            cp16(st + 20480u + (uint32_t)arow * 80u + (uint32_t)akc * 16u, BH + bIdx); \
            cp16(st + 30720u + (uint32_t)arow * 80u + (uint32_t)akc * 16u, BL + bIdx); \
        } else { \
            const ll bIdx = (ll)(k0i + bkr) * ldb + n0 + bnc * 8; \
            cp16(st + 20480u + (uint32_t)bkr * 272u + (uint32_t)bnc * 16u, BH + bIdx); \
            cp16(st + 30720u + (uint32_t)bkr * 272u + (uint32_t)bnc * 16u, BL + bIdx); \
        } }

    const int nIter = K >> 5;
    ISSUE(0); CP_COMMIT();
    ISSUE(1); CP_COMMIT();

    for (int it = 0; it < nIter; ++it) {
        if (it + 1 < nIter) { CP_WAIT1(); } else { CP_WAIT0(); }
        __syncthreads();
        if (it + 2 < nIter) ISSUE(it + 2);
        CP_COMMIT();

        const uint32_t stb = sb + (uint32_t)(it % 3) * 40960u;
        #pragma unroll
        for (int kk = 0; kk < 2; ++kk) {
            uint32_t ahi[2][4], alo[2][4], bhi[2][4], blo[2][4];
            const uint32_t akk = aLane + (uint32_t)(kk * 32);
            #pragma unroll
            for (int mi = 0; mi < 2; ++mi) {
                const uint32_t off = akk + (uint32_t)(mi * 16) * 80u;
                ldmx4(ahi[mi], stb + off);
                ldmx4(alo[mi], stb + 10240u + off);
            }
            if (flags & F_TRANS) {
                const uint32_t bkk = bLaneNT + (uint32_t)(kk * 32);
                #pragma unroll
                for (int nj = 0; nj < 2; ++nj) {
                    const uint32_t off = bkk + (uint32_t)(nj * 16) * 80u;
                    ldmx4(bhi[nj], stb + 20480u + off);
                    ldmx4(blo[nj], stb + 30720u + off);
                }
            } else {
                const uint32_t bkk = bLaneNN + (uint32_t)(kk * 16) * 272u;
                #pragma unroll
                for (int nj = 0; nj < 2; ++nj) {
                    const uint32_t off = bkk + (uint32_t)(nj * 16) * 2u;
                    ldmx4t(bhi[nj], stb + 20480u + off);
                    ldmx4t(blo[nj], stb + 30720u + off);
                }
            }
            #pragma unroll
            for (int mi = 0; mi < 2; ++mi)
                #pragma unroll
                for (int jj = 0; jj < 4; ++jj) {
                    const uint32_t* bh = &bhi[jj >> 1][(jj & 1) * 2];
                    const uint32_t* bl = &blo[jj >> 1][(jj & 1) * 2];
                    mma16816(acc[mi][jj], ahi[mi], bh);
                    mma16816(acc[mi][jj], ahi[mi], bl);
                    mma16816(acc[mi][jj], alo[mi], bh);
                }
        }
    }
    __syncthreads();
#undef ISSUE

    const int g = lane >> 2, t = lane & 3;
    if (flags & F_EXP) {
        float* rowst = (float*)smem;
        float rp[2][2] = {{0.f, 0.f}, {0.f, 0.f}};
        #pragma unroll
        for (int mi = 0; mi < 2; ++mi) {
            const ll r0 = m0 + wm0 + mi * 16 + g, r1 = r0 + 8;
            float ai0 = 0.f, ai1 = 0.f;
            if (flags & F_ADDNORM) {
                ai0 = AddInv[ziAi + r0] * addScale;
                ai1 = AddInv[ziAi + r1] * addScale;
            }
            #pragma unroll
            for (int jj = 0; jj < 4; ++jj) {
                const int col = n0 + wn0 + jj * 8 + t * 2;
                float v00 = acc[mi][jj][0] * alpha, v01 = acc[mi][jj][1] * alpha;
                float v10 = acc[mi][jj][2] * alpha, v11 = acc[mi][jj][3] * alpha;
                if (flags & F_ADDNORM) {
                    v00 += ai0 * Add[ziAdd + r0 * ldadd + col];
                    v01 += ai0 * Add[ziAdd + r0 * ldadd + col + 1];
                    v10 += ai1 * Add[ziAdd + r1 * ldadd + col];
                    v11 += ai1 * Add[ziAdd + r1 * ldadd + col + 1];
                }
                const float e00 = __expf(v00), e01 = __expf(v01);
                const float e10 = __expf(v10), e11 = __expf(v11);
                *(float2*)&C[cBase + r0 * ldc + col] = make_float2(e00, e01);
                *(float2*)&C[cBase + r1 * ldc + col] = make_float2(e10, e11);
                rp[mi][0] += e00 + e01;
                rp[mi][1] += e10 + e11;
            }
        }
        const int cidx = (wid & 3) * 4 + t;
        rowst[(wm0 + g)      * 16 + cidx] = rp[0][0];
        rowst[(wm0 + g + 8)  * 16 + cidx] = rp[0][1];
        rowst[(wm0 + 16 + g) * 16 + cidx] = rp[1][0];
        rowst[(wm0 + 24 + g) * 16 + cidx] = rp[1][1];
        __syncthreads();
        if (tid < 128) {
            float s = 0.f;
            #pragma unroll
            for (int j = 0; j < 16; ++j) s += rowst[tid * 16 + j];
            Psum[(ziP + m0 + tid) * 32 + blockIdx.x] = s;
        }
    } else {
        #pragma unroll
        for (int mi = 0; mi < 2; ++mi) {
            #pragma unroll
            for (int jj = 0; jj < 4; ++jj) {
                const ll r0 = m0 + wm0 + mi * 16 + g, r1 = r0 + 8;
                const int col = n0 + wn0 + jj * 8 + t * 2;
                float v00 = acc[mi][jj][0], v01 = acc[mi][jj][1];
                float v10 = acc[mi][jj][2], v11 = acc[mi][jj][3];
                if (bias) {
                    const float b0 = bias[ziB + col], b1 = bias[ziB + col + 1];
                    v00 += b0; v01 += b1; v10 += b0; v11 += b1;
                }
                if (flags & F_OUTPAIR) {
                    split_store2(CH, CL, cBase + r0 * ldc + col, v00, v01);
                    split_store2(CH, CL, cBase + r1 * ldc + col, v10, v11);
                } else {
                    *(float2*)&C[cBase + r0 * ldc + col] = make_float2(v00, v01);
                    *(float2*)&C[cBase + r1 * ldc + col] = make_float2(v10, v11);
                }
            }
        }
    }
}

// ---------- ctx: probs(fp32, normalize+writeback) @ v(pair) -> cat(pair) ----------
// CTA 128x64, 256 thr, double-buffered. stage: AH 0, AL 10240, BH 20480, BL 25088; 29696 x2
__global__ void __launch_bounds__(256, 2) k_ctx(
    float* __restrict__ probs, const float* __restrict__ pinv,
    const bf16* __restrict__ vH, const bf16* __restrict__ vL,
    bf16* __restrict__ catH, bf16* __restrict__ catL)
{
    extern __shared__ __align__(16) uint8_t smem[];
    const uint32_t sb = smem_to_u32(smem);
    const int tid = threadIdx.x, wid = tid >> 5, lane = tid & 31;
    const int z = blockIdx.z, b = z >> 4, h = z & 15;
    const int m0 = blockIdx.y * 128;
    probs += (ll)z * 4194304;
    pinv  += (ll)z * 2048;
    const bf16* vh = vH + (ll)b * 2097152 + h * 64;
    const bf16* vl = vL + (ll)b * 2097152 + h * 64;
    catH += (ll)b * 2048 * 1536 + h * 64;
    catL += (ll)b * 2048 * 1536 + h * 64;

    const int wm0 = (wid >> 1) * 32, wn0 = (wid & 1) * 32;
    const uint32_t aLane = (uint32_t)(wm0 + (lane & 15)) * 80u + (uint32_t)(lane >> 4) * 16u;
    const uint32_t bLane = (uint32_t)(lane & 15) * 144u
                         + (uint32_t)(wn0 + ((lane >> 1) & 8)) * 2u;
    const int ar = tid >> 1, ahalf = tid & 1;
    const int nnr = tid >> 3;
    const uint32_t nncB = (uint32_t)(tid & 7) * 16u;
    const float aScale = pinv[m0 + ar];

    float acc[2][4][4];
    #pragma unroll
    for (int i = 0; i < 2; ++i)
        #pragma unroll
        for (int j = 0; j < 4; ++j)
            #pragma unroll
            for (int e = 0; e < 4; ++e) acc[i][j][e] = 0.0f;

    float fA[16]; uint4 bHq, bLq;

#define CLOAD(itv) { \
        const int k0 = (itv) << 5; \
        float* pa = probs + (ll)(m0 + ar) * 2048 + k0 + ahalf * 16; \
        _Pragma("unroll") for (int e = 0; e < 16; e += 4) \
            *(float4*)(fA + e) = *(const float4*)(pa + e); \
        _Pragma("unroll") for (int e = 0; e < 16; ++e) fA[e] *= aScale; \
        _Pragma("unroll") for (int e = 0; e < 16; e += 4) \
            *(float4*)(pa + e) = *(float4*)(fA + e); \
        const ll bIdx = (ll)(k0 + nnr) * 1024 + (tid & 7) * 8; \
        bHq = *(const uint4*)(vh + bIdx); \
        bLq = *(const uint4*)(vl + bIdx); \
    }
#define CSTORE(st) { \
        uint8_t* sp = smem + (st) * 29696; \
        BF8 h0, l0, h1, l1; \
        split8(fA, h0, l0); split8(fA + 8, h1, l1); \
        const uint32_t oa = (uint32_t)ar * 80u + (uint32_t)ahalf * 32u; \
        *(uint4*)(sp + oa)              = *(const uint4*)&h0; \
        *(uint4*)(sp + oa + 16)         = *(const uint4*)&h1; \
        *(uint4*)(sp + 10240 + oa)      = *(const uint4*)&l0; \
        *(uint4*)(sp + 10240 + oa + 16) = *(const uint4*)&l1; \
        const uint32_t ob = (uint32_t)nnr * 144u + nncB; \
        *(uint4*)(sp + 20480 + ob) = bHq; \
        *(uint4*)(sp + 25088 + ob) = bLq; \
    }

    CLOAD(0); CSTORE(0); __syncthreads();
    int cur = 0;
    for (int it = 0; it < 64; ++it) {
        const bool hasNext = (it + 1 < 64);
        if (hasNext) CLOAD(it + 1);
        const uint32_t stb = sb + (uint32_t)cur * 29696u;
        #pragma unroll
        for (int kk = 0; kk < 2; ++kk) {
            uint32_t ahi[2][4], alo[2][4], bhi[2][4], blo[2][4];
            const uint32_t akk = aLane + (uint32_t)(kk * 32);
            #pragma unroll
            for (int mi = 0; mi < 2; ++mi) {
                const uint32_t off = akk + (uint32_t)(mi * 16) * 80u;
                ldmx4(ahi[mi], stb + off);
                ldmx4(alo[mi], stb + 10240u + off);
            }
            const uint32_t bkk = bLane + (uint32_t)(kk * 16) * 144u;
            #pragma unroll
            for (int nj = 0; nj < 2; ++nj) {
                const uint32_t off = bkk + (uint32_t)(nj * 16) * 2u;
                ldmx4t(bhi[nj], stb + 20480u + off);
                ldmx4t(blo[nj], stb + 25088u + off);
            }
            #pragma unroll
            for (int mi = 0; mi < 2; ++mi)
                #pragma unroll
                for (int jj = 0; jj < 4; ++jj) {
                    const uint32_t* bh = &bhi[jj >> 1][(jj & 1) * 2];
                    const uint32_t* bl = &blo[jj >> 1][(jj & 1) * 2];
                    mma16816(acc[mi][jj], ahi[mi], bh);
                    mma16816(acc[mi][jj], ahi[mi], bl);
                    mma16816(acc[mi][jj], alo[mi], bh);
                }
        }
        if (hasNext) CSTORE(cur ^ 1);
        __syncthreads();
        cur ^= 1;
    }
#undef CLOAD
#undef CSTORE

    const int g = lane >> 2, t = lane & 3;
    #pragma unroll
    for (int mi = 0; mi < 2; ++mi) {
        #pragma unroll
        for (int jj = 0; jj < 4; ++jj) {
            const ll r0 = m0 + wm0 + mi * 16 + g, r1 = r0 + 8;
            const int col = wn0 + jj * 8 + t * 2;
            split_store2(catH, catL, r0 * 1536 + col, acc[mi][jj][0], acc[mi][jj][1]);
            split_store2(catH, catL, r1 * 1536 + col, acc[mi][jj][2], acc[mi][jj][3]);
        }
    }
}

// ---------- row partial sums -> inverse ----------
__global__ void __launch_bounds__(256) k_rowinv(
    const float* __restrict__ part, float* __restrict__ inv, int ncols)
{
    const int row = blockIdx.x * 8 + (threadIdx.x >> 5);
    const int lane = threadIdx.x & 31;
    float s = (lane < ncols) ? part[(ll)row * 32 + lane] : 0.f;
    #pragma unroll
    for (int o = 16; o; o >>= 1) s += __shfl_xor_sync(0xFFFFFFFFu, s, o);
    if (lane == 0) inv[row] = 1.0f / s;
}

// ---------- residual + LayerNorm ----------
__global__ void __launch_bounds__(256) k_ln_res(
    const float* __restrict__ xin, const float* __restrict__ hs,
    const float* __restrict__ g, const float* __restrict__ be,
    float* __restrict__ out)
{
    ll row = blockIdx.x;
    const float* xr = xin + row * H_;
    const float* hr = hs + row * H_;
    float* orow = out + row * H_;
    int tid = threadIdx.x;
    __shared__ float red[256];
    float v[4]; float s = 0.0f;
    #pragma unroll
    for (int i = 0; i < 4; ++i) { v[i] = xr[tid + i * 256] + hr[tid + i * 256]; s += v[i]; }
    red[tid] = s; __syncthreads();
    for (int tt = 128; tt > 0; tt >>= 1) {
        if (tid < tt) red[tid] += red[tid + tt];
        __syncthreads();
    }
    float mu = red[0] * (1.0f / H_); __syncthreads();
    float var = 0.0f;
    #pragma unroll
    for (int i = 0; i < 4; ++i) { float d = v[i] - mu; var += d * d; }
    red[tid] = var; __syncthreads();
    for (int tt = 128; tt > 0; tt >>= 1) {
        if (tid < tt) red[tid] += red[tid + tt];
        __syncthreads();
    }
    float inv = rsqrtf(red[0] * (1.0f / H_) + 1e-12f);
    #pragma unroll
    for (int i = 0; i < 4; ++i) {
        int c = tid + i * 256;
        orow[c] = (v[i] - mu) * inv * g[c] + be[c];
    }
}

// ---------- launch ----------
extern "C" void kernel_launch(void* const* d_in, const int* in_sizes, int n_in,
                              void* d_out, int out_size)
{
    const float* hs  = (const float*)d_in[0];
    const float* mc  = (const float*)d_in[1];
    const float* Wq  = (const float*)d_in[2];  const float* bq  = (const float*)d_in[3];
    const float* Wk  = (const float*)d_in[4];  const float* bk  = (const float*)d_in[5];
    const float* Wv  = (const float*)d_in[6];  const float* bv  = (const float*)d_in[7];
    const float* Wmq = (const float*)d_in[8];  const float* bmq = (const float*)d_in[9];
    const float* Wmk = (const float*)d_in[10]; const float* bmk = (const float*)d_in[11];
    const float* Wc  = (const float*)d_in[12]; const float* bc  = (const float*)d_in[13];
    const float* Wf  = (const float*)d_in[14]; const float* bf  = (const float*)d_in[15];
    const float* lg  = (const float*)d_in[16]; const float* lb  = (const float*)d_in[17];

    float* out   = (float*)d_out;
    float* probs = out + (ll)B_ * S_ * H_;

    bf16 *inH,*inL,*wH,*wL,*wmH,*wmL,*wcH,*wcL,*wfH,*wfL,*qkvH,*qkvL,*mqkH,*mqkL,*catH,*catL;
    float *b3,*bm2,*med,*x,*part,*minv,*pinv;
    cudaGetSymbolAddress((void**)&inH,  g_inH);  cudaGetSymbolAddress((void**)&inL,  g_inL);
    cudaGetSymbolAddress((void**)&wH,   g_wH);   cudaGetSymbolAddress((void**)&wL,   g_wL);
    cudaGetSymbolAddress((void**)&wmH,  g_wmH);  cudaGetSymbolAddress((void**)&wmL,  g_wmL);
    cudaGetSymbolAddress((void**)&wcH,  g_wcH);  cudaGetSymbolAddress((void**)&wcL,  g_wcL);
    cudaGetSymbolAddress((void**)&wfH,  g_wfH);  cudaGetSymbolAddress((void**)&wfL,  g_wfL);
    cudaGetSymbolAddress((void**)&qkvH, g_qkvH); cudaGetSymbolAddress((void**)&qkvL, g_qkvL);
    cudaGetSymbolAddress((void**)&mqkH, g_mqkH); cudaGetSymbolAddress((void**)&mqkL, g_mqkL);
    cudaGetSymbolAddress((void**)&catH, g_catH); cudaGetSymbolAddress((void**)&catL, g_catL);
    cudaGetSymbolAddress((void**)&b3,   g_b3);   cudaGetSymbolAddress((void**)&bm2,  g_bm2);
    cudaGetSymbolAddress((void**)&med,  g_med);  cudaGetSymbolAddress((void**)&x,    g_x);
    cudaGetSymbolAddress((void**)&part, g_part); cudaGetSymbolAddress((void**)&minv, g_minv);
    cudaGetSymbolAddress((void**)&pinv, g_pinv);

    static bool attrSet = false;
    if (!attrSet) {
        cudaFuncSetAttribute(k_ps,  cudaFuncAttributeMaxDynamicSharedMemorySize, 122880);
        cudaFuncSetAttribute(k_ctx, cudaFuncAttributeMaxDynamicSharedMemorySize, 59392);
        attrSet = true;
    }

    const ll SS = 4194304, SH = 2097152, SM = 1048576;

    // prepass splits
    k_split<<<512,256>>>(hs,  inH,            inL,            524288);
    k_split<<<512,256>>>(mc,  inH + 4194304,  inL + 4194304,  524288);
    k_split<<<512,256>>>(Wq,  wH,             wL,             131072);
    k_split<<<512,256>>>(Wk,  wH + 1048576,   wL + 1048576,   131072);
    k_split<<<512,256>>>(Wv,  wH + 2097152,   wL + 2097152,   131072);
    k_split<<<512,256>>>(Wmq, wmH,            wmL,            65536);
    k_split<<<512,256>>>(Wmk, wmH + 524288,   wmL + 524288,   65536);
    k_split<<<512,256>>>(Wc,  wcH,            wcL,            65536);
    k_split<<<512,256>>>(Wf,  wfH,            wfL,            196608);
    k_pack_bias<<<1,1024>>>(bq, bk, bv, bmq, bmk);

    // QKV batched z=3 (NN, pair out)
    k_ps<<<dim3(8,32,3),512,122880>>>(inH, inL, wH, wL, b3, 0, 0,
        0, qkvH, qkvL, 0, 1024, 1024, 1024, 1024, 0, 1,
        0,0, 1048576,0, 4194304,0, 0,0, 0,0, 0,0, 1024, 1.f, 0.f, F_OUTPAIR);

    // mq|mk batched z=2 (NN, pair out). mq = [4096][512] at 0, mk at +2097152
    k_ps<<<dim3(4,32,2),512,122880>>>(inH, inL, wmH, wmL, bm2, 0, 0,
        0, mqkH, mqkL, 0, 1024, 1024, 512, 512, 0, 1,
        4194304,0, 524288,0, 2097152,0, 0,0, 0,0, 0,0, 512, 1.f, 0.f, F_OUTPAIR);

    // med scores z=2=batch (NT, exp fp32 out + Psum)
    k_ps<<<dim3(16,16,2),512,122880>>>(mqkH, mqkL, mqkH + 2097152, mqkL + 2097152, 0, 0, 0,
        med, 0, 0, part, 512, 512, 512, 2048, 0, 1,
        SM,0, SM,0, SS,0, 0,0, 0,0, 2048,0, 0, 1.f, 0.f, F_TRANS | F_EXP);
    k_rowinv<<<512,256>>>(part, minv, 16);

    // attn scores z=32 (NT, exp + med add + Psum)
    k_ps<<<dim3(16,16,32),512,122880>>>(qkvH, qkvL, qkvH + 4194304, qkvL + 4194304, 0, med, minv,
        probs, 0, 0, part, 64, 1024, 1024, 2048, 2048, 16,
        SH,64, SH,64, 16*SS,SS, SS,0, 2048,0, 32768,2048, 0,
        0.125f, 0.3f, F_TRANS | F_EXP | F_ADDNORM);
    k_rowinv<<<8192,256>>>(part, pinv, 16);

    // ctx z=32: normalize probs (writeback) @ v -> cat pair
    k_ctx<<<dim3(1,16,32),256,59392>>>(probs, pinv, qkvH + 8388608, qkvL + 8388608, catH, catL);

    // clin (NN, pair out into cat cols 1024:1536)
    k_ps<<<dim3(4,32,1),512,122880>>>(catH, catL, wcH, wcL, bc, 0, 0,
        0, catH + 1024, catL + 1024, 0, 1024, 1536, 512, 1536, 0, 1,
        0,0, 0,0, 0,0, 0,0, 0,0, 0,0, 0, 1.f, 0.f, F_OUTPAIR);

    // final (NN, fp32 out)
    k_ps<<<dim3(8,32,1),512,122880>>>(catH, catL, wfH, wfL, bf, 0, 0,
        x, 0, 0, 0, 1536, 1536, 1024, 1024, 0, 1,
        0,0, 0,0, 0,0, 0,0, 0,0, 0,0, 0, 1.f, 0.f, 0);

    k_ln_res<<<4096,256>>>(x, hs, lg, lb, out);
}

// round 15
// speedup vs baseline: 1.1595x; 1.1296x over previous
#include <cuda_runtime.h>
#include <cuda_bf16.h>
#include <cstdint>
typedef __nv_bfloat16 bf16;
typedef long long ll;

#define B_ 2
#define S_ 2048
#define H_ 1024
#define NH_ 16
#define M_ 512

// ---------- static scratch ----------
__device__ __align__(16) bf16 g_inH [8388608], g_inL [8388608];   // hs|mc pairs
__device__ __align__(16) bf16 g_wH  [3145728], g_wL  [3145728];   // Wq|Wk|Wv
__device__ __align__(16) bf16 g_wmH [1048576], g_wmL [1048576];   // Wmq|Wmk
__device__ __align__(16) bf16 g_wcH [524288],  g_wcL [524288];
__device__ __align__(16) bf16 g_wfH [1572864], g_wfL [1572864];
__device__ float g_b3 [3072];
__device__ float g_bm2[1024];
__device__ __align__(16) bf16 g_qkvH[12582912], g_qkvL[12582912]; // q|k|v pairs
__device__ __align__(16) bf16 g_mqkH[4194304],  g_mqkL[4194304];  // mq|mk pairs
__device__ float g_med [8388608];                                  // exp med scores
__device__ __align__(16) bf16 g_catH[6291456],  g_catL[6291456];  // cat pair
__device__ float g_x   [4194304];
__device__ float g_part[2097152];
__device__ float g_minv[4096];
__device__ float g_pinv[65536];

// ---------- helpers ----------
__device__ __forceinline__ uint32_t smem_to_u32(const void* p) {
    uint32_t a;
    asm("{ .reg .u64 t; cvta.to.shared.u64 t, %1; cvt.u32.u64 %0, t; }" : "=r"(a) : "l"(p));
    return a;
}
__device__ __forceinline__ void ldmx4(uint32_t* r, uint32_t a) {
    asm volatile("ldmatrix.sync.aligned.m8n8.x4.shared.b16 {%0,%1,%2,%3}, [%4];"
        : "=r"(r[0]), "=r"(r[1]), "=r"(r[2]), "=r"(r[3]) : "r"(a));
}
__device__ __forceinline__ void ldmx4t(uint32_t* r, uint32_t a) {
    asm volatile("ldmatrix.sync.aligned.m8n8.x4.trans.shared.b16 {%0,%1,%2,%3}, [%4];"
        : "=r"(r[0]), "=r"(r[1]), "=r"(r[2]), "=r"(r[3]) : "r"(a));
}
__device__ __forceinline__ void mma16816(float* d, const uint32_t* a, const uint32_t* b) {
    asm volatile(
        "mma.sync.aligned.m16n8k16.row.col.f32.bf16.bf16.f32 "
        "{%0,%1,%2,%3}, {%4,%5,%6,%7}, {%8,%9}, {%0,%1,%2,%3};"
        : "+f"(d[0]), "+f"(d[1]), "+f"(d[2]), "+f"(d[3])
        : "r"(a[0]), "r"(a[1]), "r"(a[2]), "r"(a[3]), "r"(b[0]), "r"(b[1]));
}
__device__ __forceinline__ void cp16(uint32_t dst, const void* src) {
    asm volatile("cp.async.cg.shared.global [%0], [%1], 16;" :: "r"(dst), "l"(src));
}
#define CP_COMMIT() asm volatile("cp.async.commit_group;")
#define CP_WAIT1()  asm volatile("cp.async.wait_group 1;")
#define CP_WAIT0()  asm volatile("cp.async.wait_group 0;")

struct alignas(16) BF8 { bf16 v[8]; };
__device__ __forceinline__ void split8(const float* f, BF8& hi, BF8& lo) {
    #pragma unroll
    for (int i = 0; i < 8; ++i) {
        bf16 h = __float2bfloat16(f[i]);
        hi.v[i] = h;
        lo.v[i] = __float2bfloat16(f[i] - __bfloat162float(h));
    }
}
__device__ __forceinline__ void split_store2(bf16* H, bf16* L, ll idx, float a, float b) {
    __nv_bfloat162 h, l;
    h.x = __float2bfloat16(a); h.y = __float2bfloat16(b);
    l.x = __float2bfloat16(a - __bfloat162float(h.x));
    l.y = __float2bfloat16(b - __bfloat162float(h.y));
    *(__nv_bfloat162*)(H + idx) = h;
    *(__nv_bfloat162*)(L + idx) = l;
}

#define F_TRANS   1
#define F_EXP     2
#define F_ADDNORM 4
#define F_OUTPAIR 8

// ---------- split prepass: 3 jobs per launch via z ----------
__global__ void __launch_bounds__(256) k_split3(
    const float* s0, bf16* h0, bf16* l0, int n0,
    const float* s1, bf16* h1, bf16* l1, int n1,
    const float* s2, bf16* h2, bf16* l2, int n2)
{
    const float* s; bf16 *h, *l; int n;
    if (blockIdx.z == 0)      { s = s0; h = h0; l = l0; n = n0; }
    else if (blockIdx.z == 1) { s = s1; h = h1; l = l1; n = n1; }
    else                      { s = s2; h = h2; l = l2; n = n2; }
    for (int i = blockIdx.x * 256 + threadIdx.x; i < n; i += gridDim.x * 256) {
        float f[8];
        *(float4*)(f)     = *(const float4*)(s + (ll)i * 8);
        *(float4*)(f + 4) = *(const float4*)(s + (ll)i * 8 + 4);
        BF8 hi, lo; split8(f, hi, lo);
        *(uint4*)(h + (ll)i * 8) = *(const uint4*)&hi;
        *(uint4*)(l + (ll)i * 8) = *(const uint4*)&lo;
    }
}
__global__ void __launch_bounds__(1024) k_pack_bias(
    const float* bq, const float* bk, const float* bv,
    const float* bmq, const float* bmk)
{
    int t = threadIdx.x;
    g_b3[t] = bq[t]; g_b3[1024 + t] = bk[t]; g_b3[2048 + t] = bv[t];
    if (t < 512) { g_bm2[t] = bmq[t]; g_bm2[512 + t] = bmk[t]; }
}

// ---------- cp.async 3-stage pre-split GEMM: CTA 128x128, 512 thr ----------
__global__ void __launch_bounds__(512, 1) k_ps(
    const bf16* __restrict__ AH, const bf16* __restrict__ AL,
    const bf16* __restrict__ BH, const bf16* __restrict__ BL,
    const float* __restrict__ bias, const float* __restrict__ Add,
    const float* __restrict__ AddInv,
    float* __restrict__ C, bf16* __restrict__ CH, bf16* __restrict__ CL,
    float* __restrict__ Psum,
    int K, int lda, int ldb, int ldc, int ldadd, int zdiv,
    ll sA1, ll sA0, ll sB1, ll sB0, ll sC1, ll sC0,
    ll sAdd1, ll sAdd0, ll sAi1, ll sAi0, ll sP1, ll sP0, ll sBias1,
    float alpha, float addScale, int flags)
{
    extern __shared__ __align__(16) uint8_t smem[];
    const uint32_t sb = smem_to_u32(smem);
    const int tid = threadIdx.x, wid = tid >> 5, lane = tid & 31;
    const int z = blockIdx.z, z1 = z / zdiv, z0 = z % zdiv;
    AH += z1 * sA1 + z0 * sA0;  AL += z1 * sA1 + z0 * sA0;
    BH += z1 * sB1 + z0 * sB0;  BL += z1 * sB1 + z0 * sB0;
    const ll cBase = z1 * sC1 + z0 * sC0;
    const ll ziAdd = z1 * sAdd1 + z0 * sAdd0;
    const ll ziAi  = z1 * sAi1 + z0 * sAi0;
    const ll ziP   = z1 * sP1 + z0 * sP0;
    const ll ziB   = z1 * sBias1;

    const int m0 = blockIdx.y * 128, n0 = blockIdx.x * 128;
    const int wm0 = (wid >> 2) * 32, wn0 = (wid & 3) * 32;

    const uint32_t aLane = (uint32_t)(wm0 + (lane & 15)) * 80u + (uint32_t)(lane >> 4) * 16u;
    const uint32_t bLaneNT = (uint32_t)(wn0 + ((lane >> 1) & 8) + (lane & 7)) * 80u
                           + (uint32_t)(lane & 8) * 2u;
    const uint32_t bLaneNN = (uint32_t)(lane & 15) * 272u
                           + (uint32_t)(wn0 + ((lane >> 1) & 8)) * 2u;

    const int arow = tid >> 2, akc = tid & 3;
    const int bkr  = tid >> 4, bnc = tid & 15;

    float acc[2][4][4];
    #pragma unroll
    for (int i = 0; i < 2; ++i)
        #pragma unroll
        for (int j = 0; j < 4; ++j)
            #pragma unroll
            for (int e = 0; e < 4; ++e) acc[i][j][e] = 0.0f;

#define ISSUE(itv) { \
        const int k0i = (itv) << 5; \
        const uint32_t st = sb + (uint32_t)((itv) % 3) * 40960u; \
        const ll aIdx = (ll)(m0 + arow) * lda + k0i + akc * 8; \
        cp16(st + (uint32_t)arow * 80u + (uint32_t)akc * 16u, AH + aIdx); \
        cp16(st + 10240u + (uint32_t)arow * 80u + (uint32_t)akc * 16u, AL + aIdx); \
        if (flags & F_TRANS) { \
            const ll bIdx = (ll)(n0 + arow) * ldb + k0i + akc * 8; \
            cp16(st + 20480u + (uint32_t)arow * 80u + (uint32_t)akc * 16u, BH + bIdx); \
            cp16(st + 30720u + (uint32_t)arow * 80u + (uint32_t)akc * 16u, BL + bIdx); \
        } else { \
            const ll bIdx = (ll)(k0i + bkr) * ldb + n0 + bnc * 8; \
            cp16(st + 20480u + (uint32_t)bkr * 272u + (uint32_t)bnc * 16u, BH + bIdx); \
            cp16(st + 30720u + (uint32_t)bkr * 272u + (uint32_t)bnc * 16u, BL + bIdx); \
        } }

    const int nIter = K >> 5;
    ISSUE(0); CP_COMMIT();
    ISSUE(1); CP_COMMIT();

    for (int it = 0; it < nIter; ++it) {
        if (it + 1 < nIter) { CP_WAIT1(); } else { CP_WAIT0(); }
        __syncthreads();
        if (it + 2 < nIter) ISSUE(it + 2);
        CP_COMMIT();

        const uint32_t stb = sb + (uint32_t)(it % 3) * 40960u;
        #pragma unroll
        for (int kk = 0; kk < 2; ++kk) {
            uint32_t ahi[2][4], alo[2][4], bhi[2][4], blo[2][4];
            const uint32_t akk = aLane + (uint32_t)(kk * 32);
            #pragma unroll
            for (int mi = 0; mi < 2; ++mi) {
                const uint32_t off = akk + (uint32_t)(mi * 16) * 80u;
                ldmx4(ahi[mi], stb + off);
                ldmx4(alo[mi], stb + 10240u + off);
            }
            if (flags & F_TRANS) {
                const uint32_t bkk = bLaneNT + (uint32_t)(kk * 32);
                #pragma unroll
                for (int nj = 0; nj < 2; ++nj) {
                    const uint32_t off = bkk + (uint32_t)(nj * 16) * 80u;
                    ldmx4(bhi[nj], stb + 20480u + off);
                    ldmx4(blo[nj], stb + 30720u + off);
                }
            } else {
                const uint32_t bkk = bLaneNN + (uint32_t)(kk * 16) * 272u;
                #pragma unroll
                for (int nj = 0; nj < 2; ++nj) {
                    const uint32_t off = bkk + (uint32_t)(nj * 16) * 2u;
                    ldmx4t(bhi[nj], stb + 20480u + off);
                    ldmx4t(blo[nj], stb + 30720u + off);
                }
            }
            #pragma unroll
            for (int mi = 0; mi < 2; ++mi)
                #pragma unroll
                for (int jj = 0; jj < 4; ++jj) {
                    const uint32_t* bh = &bhi[jj >> 1][(jj & 1) * 2];
                    const uint32_t* bl = &blo[jj >> 1][(jj & 1) * 2];
                    mma16816(acc[mi][jj], ahi[mi], bh);
                    mma16816(acc[mi][jj], ahi[mi], bl);
                    mma16816(acc[mi][jj], alo[mi], bh);
                }
        }
    }
    __syncthreads();
#undef ISSUE

    const int g = lane >> 2, t = lane & 3;
    if (flags & F_EXP) {
        float* rowst = (float*)smem;
        float rp[2][2] = {{0.f, 0.f}, {0.f, 0.f}};
        #pragma unroll
        for (int mi = 0; mi < 2; ++mi) {
            const ll r0 = m0 + wm0 + mi * 16 + g, r1 = r0 + 8;
            float ai0 = 0.f, ai1 = 0.f;
            if (flags & F_ADDNORM) {
                ai0 = AddInv[ziAi + r0] * addScale;
                ai1 = AddInv[ziAi + r1] * addScale;
            }
            #pragma unroll
            for (int jj = 0; jj < 4; ++jj) {
                const int col = n0 + wn0 + jj * 8 + t * 2;
                float v00 = acc[mi][jj][0] * alpha, v01 = acc[mi][jj][1] * alpha;
                float v10 = acc[mi][jj][2] * alpha, v11 = acc[mi][jj][3] * alpha;
                if (flags & F_ADDNORM) {
                    float2 a0 = *(const float2*)&Add[ziAdd + r0 * ldadd + col];
                    float2 a1 = *(const float2*)&Add[ziAdd + r1 * ldadd + col];
                    v00 += ai0 * a0.x; v01 += ai0 * a0.y;
                    v10 += ai1 * a1.x; v11 += ai1 * a1.y;
                }
                const float e00 = __expf(v00), e01 = __expf(v01);
                const float e10 = __expf(v10), e11 = __expf(v11);
                *(float2*)&C[cBase + r0 * ldc + col] = make_float2(e00, e01);
                *(float2*)&C[cBase + r1 * ldc + col] = make_float2(e10, e11);
                rp[mi][0] += e00 + e01;
                rp[mi][1] += e10 + e11;
            }
        }
        const int cidx = (wid & 3) * 4 + t;
        rowst[(wm0 + g)      * 16 + cidx] = rp[0][0];
        rowst[(wm0 + g + 8)  * 16 + cidx] = rp[0][1];
        rowst[(wm0 + 16 + g) * 16 + cidx] = rp[1][0];
        rowst[(wm0 + 24 + g) * 16 + cidx] = rp[1][1];
        __syncthreads();
        if (tid < 128) {
            float s = 0.f;
            #pragma unroll
            for (int j = 0; j < 16; ++j) s += rowst[tid * 16 + j];
            Psum[(ziP + m0 + tid) * 32 + blockIdx.x] = s;
        }
    } else {
        #pragma unroll
        for (int mi = 0; mi < 2; ++mi) {
            #pragma unroll
            for (int jj = 0; jj < 4; ++jj) {
                const ll r0 = m0 + wm0 + mi * 16 + g, r1 = r0 + 8;
                const int col = n0 + wn0 + jj * 8 + t * 2;
                float v00 = acc[mi][jj][0], v01 = acc[mi][jj][1];
                float v10 = acc[mi][jj][2], v11 = acc[mi][jj][3];
                if (bias) {
                    const float b0 = bias[ziB + col], b1 = bias[ziB + col + 1];
                    v00 += b0; v01 += b1; v10 += b0; v11 += b1;
                }
                if (flags & F_OUTPAIR) {
                    split_store2(CH, CL, cBase + r0 * ldc + col, v00, v01);
                    split_store2(CH, CL, cBase + r1 * ldc + col, v10, v11);
                } else {
                    *(float2*)&C[cBase + r0 * ldc + col] = make_float2(v00, v01);
                    *(float2*)&C[cBase + r1 * ldc + col] = make_float2(v10, v11);
                }
            }
        }
    }
}

// ---------- attn scores: 4 N-tiles per CTA, A resident, B double-buffered ----------
// smem: AH 0 (18432), AL 18432, B0H 36864, B0L 55296, B1H 73728, B1L 92160,
//       rowst 110592 (8192). total 118784.
__global__ void __launch_bounds__(512, 1) k_attn(
    const bf16* __restrict__ qH, const bf16* __restrict__ qL,
    const bf16* __restrict__ kH, const bf16* __restrict__ kL,
    const float* __restrict__ med, const float* __restrict__ minv,
    float* __restrict__ probs, float* __restrict__ Psum)
{
    extern __shared__ __align__(16) uint8_t smem[];
    const uint32_t sb = smem_to_u32(smem);
    const int tid = threadIdx.x, wid = tid >> 5, lane = tid & 31;
    const int z = blockIdx.z, b = z >> 4, h = z & 15;
    const int m0 = blockIdx.y * 128;
    const int bx = blockIdx.x;                   // n-group 0..3

    const bf16* qh = qH + (ll)b * 2097152 + h * 64;
    const bf16* ql = qL + (ll)b * 2097152 + h * 64;
    const bf16* kh = kH + (ll)b * 2097152 + h * 64;
    const bf16* kl = kL + (ll)b * 2097152 + h * 64;
    const float* medb = med + (ll)b * 4194304;
    const float* mib  = minv + (ll)b * 2048;
    float* pz = probs + (ll)z * 4194304;
    const ll psBase = (ll)z * 2048;

    const int wm0 = (wid >> 2) * 32, wn0 = (wid & 3) * 32;
    const uint32_t aLane = (uint32_t)(wm0 + (lane & 15)) * 144u + (uint32_t)(lane >> 4) * 16u;
    const uint32_t bLane = (uint32_t)(wn0 + ((lane >> 1) & 8) + (lane & 7)) * 144u
                         + (uint32_t)(lane & 8) * 2u;

    const int grow = tid >> 2;                   // 0..127
    const int gch  = tid & 3;                    // chunk base

    // load A (both halves) — one group
#define A_ISSUE() { \
        _Pragma("unroll") for (int c2 = 0; c2 < 2; ++c2) { \
            const int c = gch + c2 * 4; \
            const ll idx = (ll)(m0 + grow) * 1024 + c * 8; \
            cp16(sb + (uint32_t)grow * 144u + (uint32_t)c * 16u, qh + idx); \
            cp16(sb + 18432u + (uint32_t)grow * 144u + (uint32_t)c * 16u, ql + idx); \
        } }
#define B_ISSUE(nt) { \
        const uint32_t bb = sb + 36864u + (uint32_t)((nt) & 1) * 36864u; \
        const int nb = (bx * 4 + (nt)) * 128; \
        _Pragma("unroll") for (int c2 = 0; c2 < 2; ++c2) { \
            const int c = gch + c2 * 4; \
            const ll idx = (ll)(nb + grow) * 1024 + c * 8; \
            cp16(bb + (uint32_t)grow * 144u + (uint32_t)c * 16u, kh + idx); \
            cp16(bb + 18432u + (uint32_t)grow * 144u + (uint32_t)c * 16u, kl + idx); \
        } }

    A_ISSUE(); B_ISSUE(0); CP_COMMIT();   // G0 = {A, B0}
    B_ISSUE(1); CP_COMMIT();              // G1 = {B1}

    float* rowst = (float*)(smem + 110592);
    const int g = lane >> 2, t = lane & 3;

    for (int nt = 0; nt < 4; ++nt) {
        if (nt < 3) { CP_WAIT1(); } else { CP_WAIT0(); }
        __syncthreads();

        float acc[2][4][4];
        #pragma unroll
        for (int i = 0; i < 2; ++i)
            #pragma unroll
            for (int j = 0; j < 4; ++j)
                #pragma unroll
                for (int e = 0; e < 4; ++e) acc[i][j][e] = 0.0f;

        const uint32_t bb = sb + 36864u + (uint32_t)(nt & 1) * 36864u;
        #pragma unroll
        for (int kk = 0; kk < 4; ++kk) {
            uint32_t ahi[2][4], alo[2][4], bhi[2][4], blo[2][4];
            const uint32_t akk = aLane + (uint32_t)(kk * 32);
            #pragma unroll
            for (int mi = 0; mi < 2; ++mi) {
                const uint32_t off = akk + (uint32_t)(mi * 16) * 144u;
                ldmx4(ahi[mi], sb + off);
                ldmx4(alo[mi], sb + 18432u + off);
            }
            const uint32_t bkk = bLane + (uint32_t)(kk * 32);
            #pragma unroll
            for (int nj = 0; nj < 2; ++nj) {
                const uint32_t off = bkk + (uint32_t)(nj * 16) * 144u;
                ldmx4(bhi[nj], bb + off);
                ldmx4(blo[nj], bb + 18432u + off);
            }
            #pragma unroll
            for (int mi = 0; mi < 2; ++mi)
                #pragma unroll
                for (int jj = 0; jj < 4; ++jj) {
                    const uint32_t* bh = &bhi[jj >> 1][(jj & 1) * 2];
                    const uint32_t* bl = &blo[jj >> 1][(jj & 1) * 2];
                    mma16816(acc[mi][jj], ahi[mi], bh);
                    mma16816(acc[mi][jj], ahi[mi], bl);
                    mma16816(acc[mi][jj], alo[mi], bh);
                }
        }
        __syncthreads();                  // all warps done reading B buf (nt&1)
        if (nt + 2 < 4) { B_ISSUE(nt + 2); CP_COMMIT(); }

        // ---- epilogue for this n-tile
        const int n0 = (bx * 4 + nt) * 128;
        float rp[2][2] = {{0.f, 0.f}, {0.f, 0.f}};
        #pragma unroll
        for (int mi = 0; mi < 2; ++mi) {
            const ll r0 = m0 + wm0 + mi * 16 + g, r1 = r0 + 8;
            const float ai0 = mib[r0] * 0.3f;
            const float ai1 = mib[r1] * 0.3f;
            #pragma unroll
            for (int jj = 0; jj < 4; ++jj) {
                const int col = n0 + wn0 + jj * 8 + t * 2;
                float2 a0 = *(const float2*)&medb[r0 * 2048 + col];
                float2 a1 = *(const float2*)&medb[r1 * 2048 + col];
                const float e00 = __expf(acc[mi][jj][0] * 0.125f + ai0 * a0.x);
                const float e01 = __expf(acc[mi][jj][1] * 0.125f + ai0 * a0.y);
                const float e10 = __expf(acc[mi][jj][2] * 0.125f + ai1 * a1.x);
                const float e11 = __expf(acc[mi][jj][3] * 0.125f + ai1 * a1.y);
                *(float2*)&pz[r0 * 2048 + col] = make_float2(e00, e01);
                *(float2*)&pz[r1 * 2048 + col] = make_float2(e10, e11);
                rp[mi][0] += e00 + e01;
                rp[mi][1] += e10 + e11;
            }
        }
        const int cidx = (wid & 3) * 4 + t;
        rowst[(wm0 + g)      * 16 + cidx] = rp[0][0];
        rowst[(wm0 + g + 8)  * 16 + cidx] = rp[0][1];
        rowst[(wm0 + 16 + g) * 16 + cidx] = rp[1][0];
        rowst[(wm0 + 24 + g) * 16 + cidx] = rp[1][1];
        __syncthreads();
        if (tid < 128) {
            float s = 0.f;
            #pragma unroll
            for (int j = 0; j < 16; ++j) s += rowst[tid * 16 + j];
            Psum[(psBase + m0 + tid) * 32 + bx * 4 + nt] = s;
        }
        __syncthreads();
    }
#undef A_ISSUE
#undef B_ISSUE
}

// ---------- ctx: probs(fp32, normalize+writeback) @ v(pair) -> cat(pair) ----------
__global__ void __launch_bounds__(256, 2) k_ctx(
    float* __restrict__ probs, const float* __restrict__ pinv,
    const bf16* __restrict__ vH, const bf16* __restrict__ vL,
    bf16* __restrict__ catH, bf16* __restrict__ catL)
{
    extern __shared__ __align__(16) uint8_t smem[];
    const uint32_t sb = smem_to_u32(smem);
    const int tid = threadIdx.x, wid = tid >> 5, lane = tid & 31;
    const int z = blockIdx.z, b = z >> 4, h = z & 15;
    const int m0 = blockIdx.y * 128;
    probs += (ll)z * 4194304;
    pinv  += (ll)z * 2048;
    const bf16* vh = vH + (ll)b * 2097152 + h * 64;
    const bf16* vl = vL + (ll)b * 2097152 + h * 64;
    catH += (ll)b * 2048 * 1536 + h * 64;
    catL += (ll)b * 2048 * 1536 + h * 64;

    const int wm0 = (wid >> 1) * 32, wn0 = (wid & 1) * 32;
    const uint32_t aLane = (uint32_t)(wm0 + (lane & 15)) * 80u + (uint32_t)(lane >> 4) * 16u;
    const uint32_t bLane = (uint32_t)(lane & 15) * 144u
                         + (uint32_t)(wn0 + ((lane >> 1) & 8)) * 2u;
    const int ar = tid >> 1, ahalf = tid & 1;
    const int nnr = tid >> 3;
    const uint32_t nncB = (uint32_t)(tid & 7) * 16u;
    const float aScale = pinv[m0 + ar];

    float acc[2][4][4];
    #pragma unroll
    for (int i = 0; i < 2; ++i)
        #pragma unroll
        for (int j = 0; j < 4; ++j)
            #pragma unroll
            for (int e = 0; e < 4; ++e) acc[i][j][e] = 0.0f;

    float fA[16]; uint4 bHq, bLq;

#define CLOAD(itv) { \
        const int k0 = (itv) << 5; \
        float* pa = probs + (ll)(m0 + ar) * 2048 + k0 + ahalf * 16; \
        _Pragma("unroll") for (int e = 0; e < 16; e += 4) \
            *(float4*)(fA + e) = *(const float4*)(pa + e); \
        _Pragma("unroll") for (int e = 0; e < 16; ++e) fA[e] *= aScale; \
        _Pragma("unroll") for (int e = 0; e < 16; e += 4) \
            *(float4*)(pa + e) = *(float4*)(fA + e); \
        const ll bIdx = (ll)(k0 + nnr) * 1024 + (tid & 7) * 8; \
        bHq = *(const uint4*)(vh + bIdx); \
        bLq = *(const uint4*)(vl + bIdx); \
    }
#define CSTORE(st) { \
        uint8_t* sp = smem + (st) * 29696; \
        BF8 h0, l0, h1, l1; \
        split8(fA, h0, l0); split8(fA + 8, h1, l1); \
        const uint32_t oa = (uint32_t)ar * 80u + (uint32_t)ahalf * 32u; \
        *(uint4*)(sp + oa)              = *(const uint4*)&h0; \
        *(uint4*)(sp + oa + 16)         = *(const uint4*)&h1; \
        *(uint4*)(sp + 10240 + oa)      = *(const uint4*)&l0; \
        *(uint4*)(sp + 10240 + oa + 16) = *(const uint4*)&l1; \
        const uint32_t ob = (uint32_t)nnr * 144u + nncB; \
        *(uint4*)(sp + 20480 + ob) = bHq; \
        *(uint4*)(sp + 25088 + ob) = bLq; \
    }

    CLOAD(0); CSTORE(0); __syncthreads();
    int cur = 0;
    for (int it = 0; it < 64; ++it) {
        const bool hasNext = (it + 1 < 64);
        if (hasNext) CLOAD(it + 1);
        const uint32_t stb = sb + (uint32_t)cur * 29696u;
        #pragma unroll
        for (int kk = 0; kk < 2; ++kk) {
            uint32_t ahi[2][4], alo[2][4], bhi[2][4], blo[2][4];
            const uint32_t akk = aLane + (uint32_t)(kk * 32);
            #pragma unroll
            for (int mi = 0; mi < 2; ++mi) {
                const uint32_t off = akk + (uint32_t)(mi * 16) * 80u;
                ldmx4(ahi[mi], stb + off);
                ldmx4(alo[mi], stb + 10240u + off);
            }
            const uint32_t bkk = bLane + (uint32_t)(kk * 16) * 144u;
            #pragma unroll
            for (int nj = 0; nj < 2; ++nj) {
                const uint32_t off = bkk + (uint32_t)(nj * 16) * 2u;
                ldmx4t(bhi[nj], stb + 20480u + off);
                ldmx4t(blo[nj], stb + 25088u + off);
            }
            #pragma unroll
            for (int mi = 0; mi < 2; ++mi)
                #pragma unroll
                for (int jj = 0; jj < 4; ++jj) {
                    const uint32_t* bh = &bhi[jj >> 1][(jj & 1) * 2];
                    const uint32_t* bl = &blo[jj >> 1][(jj & 1) * 2];
                    mma16816(acc[mi][jj], ahi[mi], bh);
                    mma16816(acc[mi][jj], ahi[mi], bl);
                    mma16816(acc[mi][jj], alo[mi], bh);
                }
        }
        if (hasNext) CSTORE(cur ^ 1);
        __syncthreads();
        cur ^= 1;
    }
#undef CLOAD
#undef CSTORE

    const int g = lane >> 2, t = lane & 3;
    #pragma unroll
    for (int mi = 0; mi < 2; ++mi) {
        #pragma unroll
        for (int jj = 0; jj < 4; ++jj) {
            const ll r0 = m0 + wm0 + mi * 16 + g, r1 = r0 + 8;
            const int col = wn0 + jj * 8 + t * 2;
            split_store2(catH, catL, r0 * 1536 + col, acc[mi][jj][0], acc[mi][jj][1]);
            split_store2(catH, catL, r1 * 1536 + col, acc[mi][jj][2], acc[mi][jj][3]);
        }
    }
}

// ---------- row partial sums -> inverse ----------
__global__ void __launch_bounds__(256) k_rowinv(
    const float* __restrict__ part, float* __restrict__ inv, int ncols)
{
    const int row = blockIdx.x * 8 + (threadIdx.x >> 5);
    const int lane = threadIdx.x & 31;
    float s = (lane < ncols) ? part[(ll)row * 32 + lane] : 0.f;
    #pragma unroll
    for (int o = 16; o; o >>= 1) s += __shfl_xor_sync(0xFFFFFFFFu, s, o);
    if (lane == 0) inv[row] = 1.0f / s;
}

// ---------- residual + LayerNorm ----------
__global__ void __launch_bounds__(256) k_ln_res(
    const float* __restrict__ xin, const float* __restrict__ hs,
    const float* __restrict__ g, const float* __restrict__ be,
    float* __restrict__ out)
{
    ll row = blockIdx.x;
    const float* xr = xin + row * H_;
    const float* hr = hs + row * H_;
    float* orow = out + row * H_;
    int tid = threadIdx.x;
    __shared__ float red[256];
    float v[4]; float s = 0.0f;
    #pragma unroll
    for (int i = 0; i < 4; ++i) { v[i] = xr[tid + i * 256] + hr[tid + i * 256]; s += v[i]; }
    red[tid] = s; __syncthreads();
    for (int tt = 128; tt > 0; tt >>= 1) {
        if (tid < tt) red[tid] += red[tid + tt];
        __syncthreads();
    }
    float mu = red[0] * (1.0f / H_); __syncthreads();
    float var = 0.0f;
    #pragma unroll
    for (int i = 0; i < 4; ++i) { float d = v[i] - mu; var += d * d; }
    red[tid] = var; __syncthreads();
    for (int tt = 128; tt > 0; tt >>= 1) {
        if (tid < tt) red[tid] += red[tid + tt];
        __syncthreads();
    }
    float inv = rsqrtf(red[0] * (1.0f / H_) + 1e-12f);
    #pragma unroll
    for (int i = 0; i < 4; ++i) {
        int c = tid + i * 256;
        orow[c] = (v[i] - mu) * inv * g[c] + be[c];
    }
}

// ---------- launch ----------
extern "C" void kernel_launch(void* const* d_in, const int* in_sizes, int n_in,
                              void* d_out, int out_size)
{
    const float* hs  = (const float*)d_in[0];
    const float* mc  = (const float*)d_in[1];
    const float* Wq  = (const float*)d_in[2];  const float* bq  = (const float*)d_in[3];
    const float* Wk  = (const float*)d_in[4];  const float* bk  = (const float*)d_in[5];
    const float* Wv  = (const float*)d_in[6];  const float* bv  = (const float*)d_in[7];
    const float* Wmq = (const float*)d_in[8];  const float* bmq = (const float*)d_in[9];
    const float* Wmk = (const float*)d_in[10]; const float* bmk = (const float*)d_in[11];
    const float* Wc  = (const float*)d_in[12]; const float* bc  = (const float*)d_in[13];
    const float* Wf  = (const float*)d_in[14]; const float* bf  = (const float*)d_in[15];
    const float* lg  = (const float*)d_in[16]; const float* lb  = (const float*)d_in[17];

    float* out   = (float*)d_out;
    float* probs = out + (ll)B_ * S_ * H_;

    bf16 *inH,*inL,*wH,*wL,*wmH,*wmL,*wcH,*wcL,*wfH,*wfL,*qkvH,*qkvL,*mqkH,*mqkL,*catH,*catL;
    float *b3,*bm2,*med,*x,*part,*minv,*pinv;
    cudaGetSymbolAddress((void**)&inH,  g_inH);  cudaGetSymbolAddress((void**)&inL,  g_inL);
    cudaGetSymbolAddress((void**)&wH,   g_wH);   cudaGetSymbolAddress((void**)&wL,   g_wL);
    cudaGetSymbolAddress((void**)&wmH,  g_wmH);  cudaGetSymbolAddress((void**)&wmL,  g_wmL);
    cudaGetSymbolAddress((void**)&wcH,  g_wcH);  cudaGetSymbolAddress((void**)&wcL,  g_wcL);
    cudaGetSymbolAddress((void**)&wfH,  g_wfH);  cudaGetSymbolAddress((void**)&wfL,  g_wfL);
    cudaGetSymbolAddress((void**)&qkvH, g_qkvH); cudaGetSymbolAddress((void**)&qkvL, g_qkvL);
    cudaGetSymbolAddress((void**)&mqkH, g_mqkH); cudaGetSymbolAddress((void**)&mqkL, g_mqkL);
    cudaGetSymbolAddress((void**)&catH, g_catH); cudaGetSymbolAddress((void**)&catL, g_catL);
    cudaGetSymbolAddress((void**)&b3,   g_b3);   cudaGetSymbolAddress((void**)&bm2,  g_bm2);
    cudaGetSymbolAddress((void**)&med,  g_med);  cudaGetSymbolAddress((void**)&x,    g_x);
    cudaGetSymbolAddress((void**)&part, g_part); cudaGetSymbolAddress((void**)&minv, g_minv);
    cudaGetSymbolAddress((void**)&pinv, g_pinv);

    static bool attrSet = false;
    if (!attrSet) {
        cudaFuncSetAttribute(k_ps,   cudaFuncAttributeMaxDynamicSharedMemorySize, 122880);
        cudaFuncSetAttribute(k_attn, cudaFuncAttributeMaxDynamicSharedMemorySize, 118784);
        cudaFuncSetAttribute(k_ctx,  cudaFuncAttributeMaxDynamicSharedMemorySize, 59392);
        attrSet = true;
    }

    const ll SS = 4194304, SH = 2097152, SM = 1048576;

    // prepass splits (3 jobs per launch)
    k_split3<<<dim3(512,1,3),256>>>(hs,  inH, inL, 524288,
                                    mc,  inH + 4194304, inL + 4194304, 524288,
                                    Wq,  wH, wL, 131072);
    k_split3<<<dim3(512,1,3),256>>>(Wk,  wH + 1048576, wL + 1048576, 131072,
                                    Wv,  wH + 2097152, wL + 2097152, 131072,
                                    Wmq, wmH, wmL, 65536);
    k_split3<<<dim3(512,1,3),256>>>(Wmk, wmH + 524288, wmL + 524288, 65536,
                                    Wc,  wcH, wcL, 65536,
                                    Wf,  wfH, wfL, 196608);
    k_pack_bias<<<1,1024>>>(bq, bk, bv, bmq, bmk);

    // QKV batched z=3 (NN, pair out)
    k_ps<<<dim3(8,32,3),512,122880>>>(inH, inL, wH, wL, b3, 0, 0,
        0, qkvH, qkvL, 0, 1024, 1024, 1024, 1024, 0, 1,
        0,0, 1048576,0, 4194304,0, 0,0, 0,0, 0,0, 1024, 1.f, 0.f, F_OUTPAIR);

    // mq|mk batched z=2 (NN, pair out)
    k_ps<<<dim3(4,32,2),512,122880>>>(inH, inL, wmH, wmL, bm2, 0, 0,
        0, mqkH, mqkL, 0, 1024, 1024, 512, 512, 0, 1,
        4194304,0, 524288,0, 2097152,0, 0,0, 0,0, 0,0, 512, 1.f, 0.f, F_OUTPAIR);

    // med scores z=2=batch (NT, exp fp32 out + Psum)
    k_ps<<<dim3(16,16,2),512,122880>>>(mqkH, mqkL, mqkH + 2097152, mqkL + 2097152, 0, 0, 0,
        med, 0, 0, part, 512, 512, 512, 2048, 0, 1,
        SM,0, SM,0, SS,0, 0,0, 0,0, 2048,0, 0, 1.f, 0.f, F_TRANS | F_EXP);
    k_rowinv<<<512,256>>>(part, minv, 16);

    // attn scores z=32: dedicated kernel, 4 n-tiles/CTA
    k_attn<<<dim3(4,16,32),512,118784>>>(qkvH, qkvL, qkvH + 4194304, qkvL + 4194304,
                                         med, minv, probs, part);
    k_rowinv<<<8192,256>>>(part, pinv, 16);

    // ctx z=32: normalize probs (writeback) @ v -> cat pair
    k_ctx<<<dim3(1,16,32),256,59392>>>(probs, pinv, qkvH + 8388608, qkvL + 8388608, catH, catL);

    // clin (NN, pair out into cat cols 1024:1536)
    k_ps<<<dim3(4,32,1),512,122880>>>(catH, catL, wcH, wcL, bc, 0, 0,
        0, catH + 1024, catL + 1024, 0, 1024, 1536, 512, 1536, 0, 1,
        0,0, 0,0, 0,0, 0,0, 0,0, 0,0, 0, 1.f, 0.f, F_OUTPAIR);

    // final (NN, fp32 out)
    k_ps<<<dim3(8,32,1),512,122880>>>(catH, catL, wfH, wfL, bf, 0, 0,
        x, 0, 0, 0, 1536, 1536, 1024, 1024, 0, 1,
        0,0, 0,0, 0,0, 0,0, 0,0, 0,0, 0, 1.f, 0.f, 0);

    k_ln_res<<<4096,256>>>(x, hs, lg, lb, out);
}